// round 2
// baseline (speedup 1.0000x reference)
#include <cuda_runtime.h>
#include <cstdint>

// Problem constants (fixed shapes)
#define BB   2048
#define MM   128
#define FA   62
#define FB   6
#define DD   5
#define CC   128
#define FAN  68          // FA + FB
#define ROWS 64          // rows per CTA
#define NTHR 256

struct Smem {
    float  W[FAN * CC];        // W_self, [f][c], 34816 B
    float  vxi[ROWS * (FAN+1)];// [r][f] stride 69, conflict-free per-lane reads
    float  bself[CC];
    float  sf[FAN + 1];        // rare-row summed features
    float  zbuf[CC];           // rare-row zni result
    int    edges[ROWS * DD];
    int    deg[ROWS];
    int    rare[ROWS];
    int    nrare;
};

__device__ __forceinline__ unsigned long long pack2(float x) {
    unsigned long long r;
    asm("mov.b64 %0, {%1, %1};" : "=l"(r) : "f"(x));
    return r;
}
__device__ __forceinline__ void ffma2(unsigned long long& acc,
                                      unsigned long long a,
                                      unsigned long long b) {
    asm("fma.rn.f32x2 %0, %1, %2, %0;" : "+l"(acc) : "l"(a), "l"(b));
}
__device__ __forceinline__ float2 unpack2(unsigned long long v) {
    float2 r;
    asm("mov.b64 {%0, %1}, %2;" : "=f"(r.x), "=f"(r.y) : "l"(v));
    return r;
}

__global__ __launch_bounds__(NTHR)
void tga_kernel(const float* __restrict__ atoms,
                const float* __restrict__ bonds,
                const int*   __restrict__ edges,
                const float* __restrict__ W_inner,
                const float* __restrict__ b_inner,
                const float* __restrict__ W_self,
                const float* __restrict__ b_self,
                float* __restrict__ out) {
    extern __shared__ char raw[];
    Smem& sm = *reinterpret_cast<Smem*>(raw);

    const int tid  = threadIdx.x;
    const int lane = tid & 31;
    const int warp = tid >> 5;
    const int row0 = blockIdx.x * ROWS;          // global row base; tile within one batch (64 | 128)
    const int bidx = row0 >> 7;                  // batch index

    if (tid == 0) sm.nrare = 0;
    __syncthreads();

    // ---- Stage inputs -------------------------------------------------
    // atoms -> vxi[r][0..61]  (62 floats = 31 float2 per row, 8B-aligned)
    {
        const float2* a2 = reinterpret_cast<const float2*>(atoms);
        for (int idx = tid; idx < ROWS * 31; idx += NTHR) {
            int r = idx / 31, j = idx % 31;
            float2 v = a2[(size_t)(row0 + r) * 31 + j];
            sm.vxi[r * (FAN+1) + 2*j]     = v.x;
            sm.vxi[r * (FAN+1) + 2*j + 1] = v.y;
        }
    }
    // summed bonds -> vxi[r][62..67]
    for (int idx = tid; idx < ROWS * FB; idx += NTHR) {
        int r = idx / FB, k = idx % FB;
        const float* bp = bonds + ((size_t)(row0 + r) * DD) * FB + k;
        float s = 0.f;
        #pragma unroll
        for (int d = 0; d < DD; d++) s += bp[d * FB];
        sm.vxi[r * (FAN+1) + FA + k] = s;
    }
    // edges, degree, rare-row list
    if (tid < ROWS) {
        int dg = 0;
        #pragma unroll
        for (int d = 0; d < DD; d++) {
            int e = edges[(size_t)(row0 + tid) * DD + d];
            sm.edges[tid * DD + d] = e;
            dg += (e >= 0);
        }
        sm.deg[tid] = dg;
        if (dg < DD) {                      // only these rows need zni
            int p = atomicAdd(&sm.nrare, 1);
            sm.rare[p] = tid;
        }
    }
    if (tid < CC) sm.bself[tid] = b_self[tid];
    // W_self -> smem
    {
        const float4* w4 = reinterpret_cast<const float4*>(W_self);
        float4* d4 = reinterpret_cast<float4*>(sm.W);
        for (int idx = tid; idx < FAN * CC / 4; idx += NTHR) d4[idx] = w4[idx];
    }
    __syncthreads();

    // ---- Main matvec: zxi = vxi @ W_self ------------------------------
    // warp layout: rows  = (warp>>2)*32 + lane  (lanes = rows -> W broadcast)
    //              chans = (warp&3)*32 .. +31   (16 packed f32x2 accumulators)
    const int lrow = (warp >> 2) * 32 + lane;
    const int c0   = (warp & 3) * 32;

    unsigned long long acc[16];
    #pragma unroll
    for (int j = 0; j < 16; j++) acc[j] = 0ull;

    const float* xrow = &sm.vxi[lrow * (FAN+1)];
    #pragma unroll 4
    for (int f = 0; f < FAN; f++) {
        unsigned long long x2 = pack2(xrow[f]);
        const ulonglong2* w2 = reinterpret_cast<const ulonglong2*>(&sm.W[f * CC + c0]);
        #pragma unroll
        for (int j = 0; j < 8; j++) {
            ulonglong2 w = w2[j];
            ffma2(acc[2*j],     x2, w.x);
            ffma2(acc[2*j + 1], x2, w.y);
        }
    }

    float res[32];
    #pragma unroll
    for (int j = 0; j < 16; j++) {
        float2 v = unpack2(acc[j]);
        res[2*j]     = fmaxf(v.x + sm.bself[c0 + 2*j],     0.f);
        res[2*j + 1] = fmaxf(v.y + sm.bself[c0 + 2*j + 1], 0.f);
    }

    // ---- Rare rows (deg < 5, ~3.8%): gather neighbors + W_inner matvec
    const int nr = sm.nrare;
    for (int i = 0; i < nr; i++) {
        const int r = sm.rare[i];
        if (tid < FAN) {
            float s;
            if (tid < FA) {
                s = 0.f;
                #pragma unroll
                for (int d = 0; d < DD; d++) {
                    int e = sm.edges[r * DD + d];
                    if (e >= 0)
                        s += atoms[((size_t)(bidx * MM + e)) * FA + tid];
                }
            } else {
                s = sm.vxi[r * (FAN+1) + tid];  // summed bonds part
            }
            sm.sf[tid] = s;
        }
        __syncthreads();
        if (tid < CC) {
            int dg = sm.deg[r];
            const float* Wd = W_inner + ((size_t)dg * FAN) * CC + tid;
            float z = b_inner[dg * CC + tid];
            #pragma unroll
            for (int f = 0; f < FAN; f++)
                z = fmaf(sm.sf[f], __ldg(Wd + (size_t)f * CC), z);
            sm.zbuf[tid] = fmaxf(z, 0.f);
        }
        __syncthreads();
        if (lrow == r) {
            #pragma unroll
            for (int ch = 0; ch < 32; ch++) res[ch] += sm.zbuf[c0 + ch];
        }
    }

    // ---- Store ---------------------------------------------------------
    float4* o = reinterpret_cast<float4*>(out + (size_t)(row0 + lrow) * CC + c0);
    #pragma unroll
    for (int j = 0; j < 8; j++)
        o[j] = make_float4(res[4*j], res[4*j+1], res[4*j+2], res[4*j+3]);
}

extern "C" void kernel_launch(void* const* d_in, const int* in_sizes, int n_in,
                              void* d_out, int out_size) {
    const float* atoms   = (const float*)d_in[0];
    const float* bonds   = (const float*)d_in[1];
    const int*   edges   = (const int*)  d_in[2];
    const float* W_inner = (const float*)d_in[3];
    const float* b_inner = (const float*)d_in[4];
    const float* W_self  = (const float*)d_in[5];
    const float* b_self  = (const float*)d_in[6];
    float* out = (float*)d_out;

    const int smem = (int)sizeof(Smem);
    cudaFuncSetAttribute(tga_kernel, cudaFuncAttributeMaxDynamicSharedMemorySize, smem);

    const int nrows = BB * MM;
    tga_kernel<<<nrows / ROWS, NTHR, smem>>>(atoms, bonds, edges,
                                             W_inner, b_inner, W_self, b_self, out);
}

// round 3
// speedup vs baseline: 1.0112x; 1.0112x over previous
#include <cuda_runtime.h>
#include <cstdint>

// Problem constants (fixed shapes)
#define BB   2048
#define MM   128
#define FA   62
#define FB   6
#define DD   5
#define CC   128
#define FAN  68          // FA + FB
#define ROWS 128         // rows per CTA  (== MM, one batch per CTA)
#define NTHR 256

struct Smem {
    float  W[FAN * CC];        // W_self, [f][c], 34816 B
    float  vxi[ROWS * (FAN+1)];// [r][f] stride 69, conflict-free per-lane reads
    float  bself[CC];
    float  sf[FAN + 1];        // rare-row summed features
    float  zbuf[CC];           // rare-row zni result
    int    edges[ROWS * DD];
    int    deg[ROWS];
    int    rare[ROWS];
    int    nrare;
};

__device__ __forceinline__ unsigned long long pack2(float x) {
    unsigned long long r;
    asm("mov.b64 %0, {%1, %1};" : "=l"(r) : "f"(x));
    return r;
}
__device__ __forceinline__ void ffma2(unsigned long long& acc,
                                      unsigned long long a,
                                      unsigned long long b) {
    asm("fma.rn.f32x2 %0, %1, %2, %0;" : "+l"(acc) : "l"(a), "l"(b));
}
__device__ __forceinline__ float2 unpack2(unsigned long long v) {
    float2 r;
    asm("mov.b64 {%0, %1}, %2;" : "=f"(r.x), "=f"(r.y) : "l"(v));
    return r;
}

__global__ __launch_bounds__(NTHR, 2)
void tga_kernel(const float* __restrict__ atoms,
                const float* __restrict__ bonds,
                const int*   __restrict__ edges,
                const float* __restrict__ W_inner,
                const float* __restrict__ b_inner,
                const float* __restrict__ W_self,
                const float* __restrict__ b_self,
                float* __restrict__ out) {
    extern __shared__ char raw[];
    Smem& sm = *reinterpret_cast<Smem*>(raw);

    const int tid  = threadIdx.x;
    const int lane = tid & 31;
    const int warp = tid >> 5;
    const int row0 = blockIdx.x * ROWS;   // one full batch per CTA (ROWS == MM)
    const int bidx = blockIdx.x;

    if (tid == 0) sm.nrare = 0;
    __syncthreads();

    // ---- Stage inputs -------------------------------------------------
    // atoms -> vxi[r][0..61]  (62 floats = 31 float2 per row, 8B-aligned)
    {
        const float2* a2 = reinterpret_cast<const float2*>(atoms);
        for (int idx = tid; idx < ROWS * 31; idx += NTHR) {
            int r = idx / 31, j = idx % 31;
            float2 v = a2[(size_t)(row0 + r) * 31 + j];
            sm.vxi[r * (FAN+1) + 2*j]     = v.x;
            sm.vxi[r * (FAN+1) + 2*j + 1] = v.y;
        }
    }
    // summed bonds -> vxi[r][62..67]
    for (int idx = tid; idx < ROWS * FB; idx += NTHR) {
        int r = idx / FB, k = idx % FB;
        const float* bp = bonds + ((size_t)(row0 + r) * DD) * FB + k;
        float s = 0.f;
        #pragma unroll
        for (int d = 0; d < DD; d++) s += bp[d * FB];
        sm.vxi[r * (FAN+1) + FA + k] = s;
    }
    // edges, degree, rare-row list
    if (tid < ROWS) {
        int dg = 0;
        #pragma unroll
        for (int d = 0; d < DD; d++) {
            int e = edges[(size_t)(row0 + tid) * DD + d];
            sm.edges[tid * DD + d] = e;
            dg += (e >= 0);
        }
        sm.deg[tid] = dg;
        if (dg < DD) {                      // only these rows need zni
            int p = atomicAdd(&sm.nrare, 1);
            sm.rare[p] = tid;
        }
    }
    if (tid < CC) sm.bself[tid] = b_self[tid];
    // W_self -> smem
    {
        const float4* w4 = reinterpret_cast<const float4*>(W_self);
        float4* d4 = reinterpret_cast<float4*>(sm.W);
        for (int idx = tid; idx < FAN * CC / 4; idx += NTHR) d4[idx] = w4[idx];
    }
    __syncthreads();

    // ---- Main matvec: zxi = vxi @ W_self ------------------------------
    // warp tile: 64 rows x 32 channels.
    //   rows  r0 = (warp>>2)*64 + lane, r1 = r0 + 32   (lanes = rows -> W broadcast)
    //   chans c0 = (warp&3)*32 .. +31
    // Each weight LDS.128 broadcast now feeds FOUR FFMA2 (2 rows x f32x2 pair),
    // halving L1 wavefronts per FMA vs the 1-row layout.
    const int r0 = (warp >> 2) * 64 + lane;
    const int r1 = r0 + 32;
    const int c0 = (warp & 3) * 32;

    unsigned long long acc0[16], acc1[16];
    #pragma unroll
    for (int j = 0; j < 16; j++) { acc0[j] = 0ull; acc1[j] = 0ull; }

    const float* x0 = &sm.vxi[r0 * (FAN+1)];
    const float* x1 = &sm.vxi[r1 * (FAN+1)];
    #pragma unroll 2
    for (int f = 0; f < FAN; f++) {
        unsigned long long xa = pack2(x0[f]);
        unsigned long long xb = pack2(x1[f]);
        const ulonglong2* w2 = reinterpret_cast<const ulonglong2*>(&sm.W[f * CC + c0]);
        #pragma unroll
        for (int j = 0; j < 8; j++) {
            ulonglong2 w = w2[j];
            ffma2(acc0[2*j],     xa, w.x);
            ffma2(acc0[2*j + 1], xa, w.y);
            ffma2(acc1[2*j],     xb, w.x);
            ffma2(acc1[2*j + 1], xb, w.y);
        }
    }

    float res0[32], res1[32];
    #pragma unroll
    for (int j = 0; j < 16; j++) {
        float2 b;
        b.x = sm.bself[c0 + 2*j];
        b.y = sm.bself[c0 + 2*j + 1];
        float2 v0 = unpack2(acc0[j]);
        float2 v1 = unpack2(acc1[j]);
        res0[2*j]     = fmaxf(v0.x + b.x, 0.f);
        res0[2*j + 1] = fmaxf(v0.y + b.y, 0.f);
        res1[2*j]     = fmaxf(v1.x + b.x, 0.f);
        res1[2*j + 1] = fmaxf(v1.y + b.y, 0.f);
    }

    // ---- Rare rows (deg < 5, ~3.8%): gather neighbors + W_inner matvec
    const int nr = sm.nrare;
    for (int i = 0; i < nr; i++) {
        const int r = sm.rare[i];
        if (tid < FAN) {
            float s;
            if (tid < FA) {
                s = 0.f;
                #pragma unroll
                for (int d = 0; d < DD; d++) {
                    int e = sm.edges[r * DD + d];
                    if (e >= 0)
                        s += atoms[((size_t)(bidx * MM + e)) * FA + tid];
                }
            } else {
                s = sm.vxi[r * (FAN+1) + tid];  // summed bonds part
            }
            sm.sf[tid] = s;
        }
        __syncthreads();
        if (tid < CC) {
            int dg = sm.deg[r];
            const float* Wd = W_inner + ((size_t)dg * FAN) * CC + tid;
            float z = b_inner[dg * CC + tid];
            #pragma unroll
            for (int f = 0; f < FAN; f++)
                z = fmaf(sm.sf[f], __ldg(Wd + (size_t)f * CC), z);
            sm.zbuf[tid] = fmaxf(z, 0.f);
        }
        __syncthreads();
        if (r0 == r) {
            #pragma unroll
            for (int ch = 0; ch < 32; ch++) res0[ch] += sm.zbuf[c0 + ch];
        }
        if (r1 == r) {
            #pragma unroll
            for (int ch = 0; ch < 32; ch++) res1[ch] += sm.zbuf[c0 + ch];
        }
    }

    // ---- Store ---------------------------------------------------------
    float4* o0 = reinterpret_cast<float4*>(out + (size_t)(row0 + r0) * CC + c0);
    float4* o1 = reinterpret_cast<float4*>(out + (size_t)(row0 + r1) * CC + c0);
    #pragma unroll
    for (int j = 0; j < 8; j++)
        o0[j] = make_float4(res0[4*j], res0[4*j+1], res0[4*j+2], res0[4*j+3]);
    #pragma unroll
    for (int j = 0; j < 8; j++)
        o1[j] = make_float4(res1[4*j], res1[4*j+1], res1[4*j+2], res1[4*j+3]);
}

extern "C" void kernel_launch(void* const* d_in, const int* in_sizes, int n_in,
                              void* d_out, int out_size) {
    const float* atoms   = (const float*)d_in[0];
    const float* bonds   = (const float*)d_in[1];
    const int*   edges   = (const int*)  d_in[2];
    const float* W_inner = (const float*)d_in[3];
    const float* b_inner = (const float*)d_in[4];
    const float* W_self  = (const float*)d_in[5];
    const float* b_self  = (const float*)d_in[6];
    float* out = (float*)d_out;

    const int smem = (int)sizeof(Smem);
    cudaFuncSetAttribute(tga_kernel, cudaFuncAttributeMaxDynamicSharedMemorySize, smem);

    const int nrows = BB * MM;
    tga_kernel<<<nrows / ROWS, NTHR, smem>>>(atoms, bonds, edges,
                                             W_inner, b_inner, W_self, b_self, out);
}

// round 4
// speedup vs baseline: 1.0660x; 1.0542x over previous
#include <cuda_runtime.h>
#include <cstdint>

// Problem constants (fixed shapes)
#define BB   2048
#define MM   128
#define FA   62
#define FB   6
#define DD   5
#define CC   128
#define FAN  68          // FA + FB
#define ROWS 128         // rows per CTA  (== MM, one batch per CTA)
#define NTHR 256

struct Smem {
    float  W[FAN * CC];          // W_self, [f][c], 34816 B
    float  vxi[ROWS * (FAN+1)];  // [r][f] stride 69, conflict-free per-lane reads
    float  bself[CC];
    float  sfw[8 * 72];          // per-warp rare-row summed features
    int    rare[ROWS];           // packed: row | (deg<<8)
    int    nrare;
};

__device__ __forceinline__ unsigned long long pack2(float x) {
    unsigned long long r;
    asm("mov.b64 %0, {%1, %1};" : "=l"(r) : "f"(x));
    return r;
}
__device__ __forceinline__ void ffma2(unsigned long long& acc,
                                      unsigned long long a,
                                      unsigned long long b) {
    asm("fma.rn.f32x2 %0, %1, %2, %0;" : "+l"(acc) : "l"(a), "l"(b));
}
__device__ __forceinline__ float2 unpack2(unsigned long long v) {
    float2 r;
    asm("mov.b64 {%0, %1}, %2;" : "=f"(r.x), "=f"(r.y) : "l"(v));
    return r;
}

__global__ __launch_bounds__(NTHR, 3)
void tga_kernel(const float* __restrict__ atoms,
                const float* __restrict__ bonds,
                const int*   __restrict__ edges,
                const float* __restrict__ W_inner,
                const float* __restrict__ b_inner,
                const float* __restrict__ W_self,
                const float* __restrict__ b_self,
                float* __restrict__ out) {
    extern __shared__ char raw[];
    Smem& sm = *reinterpret_cast<Smem*>(raw);

    const int tid  = threadIdx.x;
    const int lane = tid & 31;
    const int warp = tid >> 5;
    const int row0 = blockIdx.x * ROWS;   // one full batch per CTA (ROWS == MM)
    const int bidx = blockIdx.x;

    if (tid == 0) sm.nrare = 0;
    __syncthreads();

    // ---- Stage inputs -------------------------------------------------
    // atoms -> vxi[r][0..61]  (62 floats = 31 float2 per row; 32-slot padding,
    // shift/mask indexing -> no div/mod, coalesced within each row)
    {
        const float2* a2 = reinterpret_cast<const float2*>(atoms);
        #pragma unroll
        for (int idx = tid; idx < ROWS * 32; idx += NTHR) {
            int r = idx >> 5, j = idx & 31;
            if (j < 31) {
                float2 v = a2[(size_t)(row0 + r) * 31 + j];
                sm.vxi[r * (FAN+1) + 2*j]     = v.x;
                sm.vxi[r * (FAN+1) + 2*j + 1] = v.y;
            }
        }
    }
    // summed bonds -> vxi[r][62..67] (8-slot padding, shift/mask)
    #pragma unroll
    for (int idx = tid; idx < ROWS * 8; idx += NTHR) {
        int r = idx >> 3, k = idx & 7;
        if (k < FB) {
            const float* bp = bonds + ((size_t)(row0 + r) * DD) * FB + k;
            float s = 0.f;
            #pragma unroll
            for (int d = 0; d < DD; d++) s += bp[d * FB];
            sm.vxi[r * (FAN+1) + FA + k] = s;
        }
    }
    // degree + rare-row list (packed row|deg<<8)
    if (tid < ROWS) {
        int dg = 0;
        #pragma unroll
        for (int d = 0; d < DD; d++) {
            int e = edges[(size_t)(row0 + tid) * DD + d];
            dg += (e >= 0);
        }
        if (dg < DD) {                      // only these rows need zni
            int p = atomicAdd(&sm.nrare, 1);
            sm.rare[p] = tid | (dg << 8);
        }
    }
    if (tid < CC) sm.bself[tid] = b_self[tid];
    // W_self -> smem
    {
        const float4* w4 = reinterpret_cast<const float4*>(W_self);
        float4* d4 = reinterpret_cast<float4*>(sm.W);
        for (int idx = tid; idx < FAN * CC / 4; idx += NTHR) d4[idx] = w4[idx];
    }
    __syncthreads();

    // ---- Main matvec: zxi = vxi @ W_self ------------------------------
    // warp tile: 64 rows x 32 channels.
    //   rows  r0 = (warp>>2)*64 + lane, r1 = r0 + 32   (lanes = rows -> W broadcast)
    //   chans c0 = (warp&3)*32 .. +31
    const int r0 = (warp >> 2) * 64 + lane;
    const int r1 = r0 + 32;
    const int c0 = (warp & 3) * 32;

    unsigned long long acc0[16], acc1[16];
    #pragma unroll
    for (int j = 0; j < 16; j++) { acc0[j] = 0ull; acc1[j] = 0ull; }

    const float* x0 = &sm.vxi[r0 * (FAN+1)];
    const float* x1 = &sm.vxi[r1 * (FAN+1)];
    #pragma unroll 2
    for (int f = 0; f < FAN; f++) {
        unsigned long long xa = pack2(x0[f]);
        unsigned long long xb = pack2(x1[f]);
        const ulonglong2* w2 = reinterpret_cast<const ulonglong2*>(&sm.W[f * CC + c0]);
        #pragma unroll
        for (int j = 0; j < 8; j++) {
            ulonglong2 w = w2[j];
            ffma2(acc0[2*j],     xa, w.x);
            ffma2(acc0[2*j + 1], xa, w.y);
            ffma2(acc1[2*j],     xb, w.x);
            ffma2(acc1[2*j + 1], xb, w.y);
        }
    }

    // ---- Epilogue: bias + relu + STG straight from accumulators -------
    // (accumulator registers die here; nothing fp32 lives across the tail)
    {
        float4* o0 = reinterpret_cast<float4*>(out + (size_t)(row0 + r0) * CC + c0);
        float4* o1 = reinterpret_cast<float4*>(out + (size_t)(row0 + r1) * CC + c0);
        #pragma unroll
        for (int j = 0; j < 8; j++) {
            float b0 = sm.bself[c0 + 4*j + 0];
            float b1 = sm.bself[c0 + 4*j + 1];
            float b2 = sm.bself[c0 + 4*j + 2];
            float b3 = sm.bself[c0 + 4*j + 3];
            float2 a = unpack2(acc0[2*j]);
            float2 b = unpack2(acc0[2*j + 1]);
            float4 v;
            v.x = fmaxf(a.x + b0, 0.f);
            v.y = fmaxf(a.y + b1, 0.f);
            v.z = fmaxf(b.x + b2, 0.f);
            v.w = fmaxf(b.y + b3, 0.f);
            o0[j] = v;
            a = unpack2(acc1[2*j]);
            b = unpack2(acc1[2*j + 1]);
            v.x = fmaxf(a.x + b0, 0.f);
            v.y = fmaxf(a.y + b1, 0.f);
            v.z = fmaxf(b.x + b2, 0.f);
            v.w = fmaxf(b.y + b3, 0.f);
            o1[j] = v;
        }
    }

    // Order the STGs above before the RMW patches below (CTA scope).
    __syncthreads();

    // ---- Rare rows (deg < 5, ~3.8%): warp-parallel zni patch -----------
    // Each warp independently owns rare slots i = warp, warp+8, ...
    // No CTA barriers; output row is patched with a global float4 RMW.
    const int nr = sm.nrare;
    float* sfp = &sm.sfw[warp * 72];
    for (int i = warp; i < nr; i += 8) {
        const int packed = sm.rare[i];
        const int r  = packed & 0xFF;
        const int dg = packed >> 8;

        // all lanes load the row's 5 edge ids (same addr -> 1 request)
        int e[DD];
        #pragma unroll
        for (int d = 0; d < DD; d++)
            e[d] = edges[(size_t)(row0 + r) * DD + d];

        // summed features: lane covers f = lane, lane+32, lane+64
        #pragma unroll
        for (int f = lane; f < FAN; f += 32) {
            float s;
            if (f < FA) {
                s = 0.f;
                #pragma unroll
                for (int d = 0; d < DD; d++) {
                    if (e[d] >= 0)
                        s += atoms[((size_t)(bidx * MM + e[d])) * FA + f];
                }
            } else {
                s = sm.vxi[r * (FAN+1) + f];   // summed bonds part
            }
            sfp[f] = s;
        }
        __syncwarp();

        // matvec: lane owns channels 4*lane..4*lane+3 (one float4)
        const float4* bi4 = reinterpret_cast<const float4*>(b_inner) + dg * 32 + lane;
        const float4* w4  = reinterpret_cast<const float4*>(W_inner)
                            + ((size_t)dg * FAN) * 32 + lane;
        float4 z = __ldg(bi4);
        #pragma unroll
        for (int f = 0; f < FAN; f++) {
            float  s = sfp[f];
            float4 w = __ldg(w4 + (size_t)f * 32);
            z.x = fmaf(s, w.x, z.x);
            z.y = fmaf(s, w.y, z.y);
            z.z = fmaf(s, w.z, z.z);
            z.w = fmaf(s, w.w, z.w);
        }
        float4* op = reinterpret_cast<float4*>(out + (size_t)(row0 + r) * CC) + lane;
        float4 cur = *op;
        cur.x += fmaxf(z.x, 0.f);
        cur.y += fmaxf(z.y, 0.f);
        cur.z += fmaxf(z.z, 0.f);
        cur.w += fmaxf(z.w, 0.f);
        *op = cur;
        __syncwarp();
    }
}

extern "C" void kernel_launch(void* const* d_in, const int* in_sizes, int n_in,
                              void* d_out, int out_size) {
    const float* atoms   = (const float*)d_in[0];
    const float* bonds   = (const float*)d_in[1];
    const int*   edges   = (const int*)  d_in[2];
    const float* W_inner = (const float*)d_in[3];
    const float* b_inner = (const float*)d_in[4];
    const float* W_self  = (const float*)d_in[5];
    const float* b_self  = (const float*)d_in[6];
    float* out = (float*)d_out;

    const int smem = (int)sizeof(Smem);
    cudaFuncSetAttribute(tga_kernel, cudaFuncAttributeMaxDynamicSharedMemorySize, smem);

    const int nrows = BB * MM;
    tga_kernel<<<nrows / ROWS, NTHR, smem>>>(atoms, bonds, edges,
                                             W_inner, b_inner, W_self, b_self, out);
}

// round 7
// speedup vs baseline: 1.9185x; 1.7996x over previous
#include <cuda_runtime.h>
#include <cuda_bf16.h>
#include <cstdint>

// Problem constants
#define BB   2048
#define MM   128
#define FA   62
#define FB   6
#define DD   5
#define CC   128
#define FAN  68
#define NTHR 256
#define KP   80            // K padded to 5 mma-steps of 16
#define STRD 88            // smem row stride in bf16 (176 B = 16B*11 -> ldmatrix conflict-free)

// SMEM byte offsets
#define SM_AHI   0                       // 128 x 88 bf16 = 22528
#define SM_ALO   22528
#define SM_BHI   45056                   // 128n x 88k bf16
#define SM_BLO   67584
#define SM_BSELF 90112                   // float[128]
#define SM_SFW   90624                   // 8 warps * 72 floats
#define SM_RARE  92928                   // int[128]
#define SM_NRARE 93440
#define SM_TOTAL 93568

__device__ __forceinline__ uint32_t smem_to_u32(const void* p) {
    uint32_t a;
    asm("{ .reg .u64 t; cvta.to.shared.u64 t, %1; cvt.u32.u64 %0, t; }" : "=r"(a) : "l"(p));
    return a;
}
__device__ __forceinline__ void ldsm_x4(uint32_t* r, uint32_t addr) {
    asm volatile("ldmatrix.sync.aligned.m8n8.x4.shared.b16 {%0,%1,%2,%3}, [%4];"
                 : "=r"(r[0]), "=r"(r[1]), "=r"(r[2]), "=r"(r[3]) : "r"(addr));
}
__device__ __forceinline__ void mma_bf16(float* d, const uint32_t* a, const uint32_t* b) {
    asm volatile("mma.sync.aligned.m16n8k16.row.col.f32.bf16.bf16.f32 "
                 "{%0,%1,%2,%3}, {%4,%5,%6,%7}, {%8,%9}, {%0,%1,%2,%3};"
                 : "+f"(d[0]), "+f"(d[1]), "+f"(d[2]), "+f"(d[3])
                 : "r"(a[0]), "r"(a[1]), "r"(a[2]), "r"(a[3]), "r"(b[0]), "r"(b[1]));
}
// fp32 pair -> packed bf16x2 hi and lo (x = hi + lo to ~2^-18 relative)
__device__ __forceinline__ void split2(float x0, float x1, uint32_t& hi, uint32_t& lo) {
    __nv_bfloat162 h = __floats2bfloat162_rn(x0, x1);
    float h0 = __bfloat162float(__low2bfloat16(h));
    float h1 = __bfloat162float(__high2bfloat16(h));
    __nv_bfloat162 l = __floats2bfloat162_rn(x0 - h0, x1 - h1);
    hi = *reinterpret_cast<uint32_t*>(&h);
    lo = *reinterpret_cast<uint32_t*>(&l);
}

__global__ __launch_bounds__(NTHR, 2)
void tga_kernel(const float* __restrict__ atoms,
                const float* __restrict__ bonds,
                const int*   __restrict__ edges,
                const float* __restrict__ W_inner,
                const float* __restrict__ b_inner,
                const float* __restrict__ W_self,
                const float* __restrict__ b_self,
                float* __restrict__ out) {
    extern __shared__ char smem[];
    const uint32_t smem_base = smem_to_u32(smem);
    const int tid  = threadIdx.x;
    const int lane = tid & 31;
    const int warp = tid >> 5;
    const int row0 = blockIdx.x * MM;      // one batch per CTA
    const int bidx = blockIdx.x;

    if (tid == 0) *reinterpret_cast<int*>(smem + SM_NRARE) = 0;
    __syncthreads();

    // ---------------- Stage A (atoms | summed bonds) as bf16 hi/lo -----------
    // Row handled by 2 threads: shalf 0 -> k 0..39, shalf 1 -> k 40..79.
    {
        const int srow  = tid & 127;
        const int shalf = tid >> 7;
        char* ah = smem + SM_AHI + srow * (STRD * 2);
        char* al = smem + SM_ALO + srow * (STRD * 2);
        if (shalf == 0) {
            const float2* a2 = reinterpret_cast<const float2*>(atoms + (size_t)(row0 + srow) * FA);
            #pragma unroll
            for (int j = 0; j < 20; j++) {          // k = 0..39
                float2 v = a2[j];
                uint32_t hi, lo;
                split2(v.x, v.y, hi, lo);
                *reinterpret_cast<uint32_t*>(ah + 4*j) = hi;
                *reinterpret_cast<uint32_t*>(al + 4*j) = lo;
            }
        } else {
            const float2* a2 = reinterpret_cast<const float2*>(atoms + (size_t)(row0 + srow) * FA);
            #pragma unroll
            for (int j = 20; j < 31; j++) {         // k = 40..61
                float2 v = a2[j];
                uint32_t hi, lo;
                split2(v.x, v.y, hi, lo);
                *reinterpret_cast<uint32_t*>(ah + 4*j) = hi;
                *reinterpret_cast<uint32_t*>(al + 4*j) = lo;
            }
            // summed bonds -> k 62..67
            float bs[FB];
            #pragma unroll
            for (int f = 0; f < FB; f++) bs[f] = 0.f;
            const float* bp = bonds + (size_t)(row0 + srow) * DD * FB;
            #pragma unroll
            for (int d = 0; d < DD; d++)
                #pragma unroll
                for (int f = 0; f < FB; f++) bs[f] += bp[d * FB + f];
            #pragma unroll
            for (int p = 0; p < 3; p++) {
                uint32_t hi, lo;
                split2(bs[2*p], bs[2*p + 1], hi, lo);
                *reinterpret_cast<uint32_t*>(ah + 4*(31 + p)) = hi;
                *reinterpret_cast<uint32_t*>(al + 4*(31 + p)) = lo;
            }
            #pragma unroll
            for (int j = 34; j < 40; j++) {         // k pad 68..79
                *reinterpret_cast<uint32_t*>(ah + 4*j) = 0u;
                *reinterpret_cast<uint32_t*>(al + 4*j) = 0u;
            }
        }
    }

    // ---------------- Stage B = W_self^T as bf16 hi/lo  ([n][k], k-contig) ----
    for (int idx = tid; idx < FAN * CC; idx += NTHR) {
        int k = idx >> 7, n = idx & (CC - 1);       // coalesced LDG over n
        float w = W_self[idx];
        __nv_bfloat16 h = __float2bfloat16(w);
        __nv_bfloat16 l = __float2bfloat16(w - __bfloat162float(h));
        uint32_t off = (uint32_t)n * (STRD * 2) + (uint32_t)k * 2;
        *reinterpret_cast<__nv_bfloat16*>(smem + SM_BHI + off) = h;
        *reinterpret_cast<__nv_bfloat16*>(smem + SM_BLO + off) = l;
    }
    for (int idx = tid; idx < (KP - FAN) * CC; idx += NTHR) {   // k pad 68..79
        int k = FAN + (idx >> 7), n = idx & (CC - 1);
        uint32_t off = (uint32_t)n * (STRD * 2) + (uint32_t)k * 2;
        *reinterpret_cast<__nv_bfloat16*>(smem + SM_BHI + off) = __nv_bfloat16(0.f);
        *reinterpret_cast<__nv_bfloat16*>(smem + SM_BLO + off) = __nv_bfloat16(0.f);
    }

    // bias, degree + rare list
    if (tid < CC) reinterpret_cast<float*>(smem + SM_BSELF)[tid] = b_self[tid];
    if (tid < MM) {
        const int* ep = edges + (size_t)(row0 + tid) * DD;
        int dg = 0;
        #pragma unroll
        for (int d = 0; d < DD; d++) dg += (ep[d] >= 0);
        if (dg < DD) {
            int p = atomicAdd(reinterpret_cast<int*>(smem + SM_NRARE), 1);
            reinterpret_cast<int*>(smem + SM_RARE)[p] = tid | (dg << 8);
        }
    }
    __syncthreads();

    // ---------------- Tensor-core GEMM: D = Ah*Bh + Ah*Bl + Al*Bh -------------
    // warp tile: m16 (rows warp*16..+15) x n128 (16 n-tiles of 8)
    float acc[16][4];
    #pragma unroll
    for (int j = 0; j < 16; j++)
        #pragma unroll
        for (int q = 0; q < 4; q++) acc[j][q] = 0.f;

    const int wm = warp * 16;
    // per-lane invariant address pieces (bytes)
    const uint32_t arow_off = ((uint32_t)(wm + (lane & 15)) * STRD + ((lane >> 4) << 3)) * 2;
    const uint32_t brow_off = (((uint32_t)((lane & 7) + ((lane & 16) >> 1))) * STRD) * 2 + (lane & 8) * 2;

    #pragma unroll 1
    for (int term = 0; term < 3; term++) {
        const uint32_t abase = smem_base + (term == 2 ? SM_ALO : SM_AHI) + arow_off;
        const uint32_t bbase = smem_base + (term == 1 ? SM_BLO : SM_BHI) + brow_off;
        #pragma unroll
        for (int kk = 0; kk < 5; kk++) {
            uint32_t a[4];
            ldsm_x4(a, abase + kk * 32);
            #pragma unroll
            for (int jp = 0; jp < 8; jp++) {
                uint32_t b[4];
                ldsm_x4(b, bbase + (uint32_t)jp * 16 * (STRD * 2) + kk * 32);
                mma_bf16(acc[2*jp],     a, b);
                mma_bf16(acc[2*jp + 1], a, b + 2);
            }
        }
    }

    // ---------------- Epilogue: bias + relu + STG.64 --------------------------
    {
        const float* bs = reinterpret_cast<const float*>(smem + SM_BSELF);
        const int r0 = wm + (lane >> 2);
        const int c00 = 2 * (lane & 3);
        float* orow0 = out + (size_t)(row0 + r0) * CC;
        float* orow1 = out + (size_t)(row0 + r0 + 8) * CC;
        #pragma unroll
        for (int j = 0; j < 16; j++) {
            int c = 8 * j + c00;
            float b0 = bs[c], b1 = bs[c + 1];
            float2 v0, v1;
            v0.x = fmaxf(acc[j][0] + b0, 0.f);
            v0.y = fmaxf(acc[j][1] + b1, 0.f);
            v1.x = fmaxf(acc[j][2] + b0, 0.f);
            v1.y = fmaxf(acc[j][3] + b1, 0.f);
            *reinterpret_cast<float2*>(orow0 + c) = v0;
            *reinterpret_cast<float2*>(orow1 + c) = v1;
        }
    }
    __syncthreads();   // order epilogue STGs before rare-row RMW (same CTA/SM)

    // ---------------- Rare rows (deg<5, ~3.8%): warp-parallel zni patch -------
    const int nr = *reinterpret_cast<int*>(smem + SM_NRARE);
    float* sfp = reinterpret_cast<float*>(smem + SM_SFW) + warp * 72;
    for (int i = warp; i < nr; i += 8) {
        int packed = reinterpret_cast<int*>(smem + SM_RARE)[i];
        int r  = packed & 0xFF;
        int dg = packed >> 8;
        int e[DD];
        #pragma unroll
        for (int d = 0; d < DD; d++) e[d] = edges[(size_t)(row0 + r) * DD + d];
        #pragma unroll
        for (int f = lane; f < FAN; f += 32) {
            float s = 0.f;
            if (f < FA) {
                #pragma unroll
                for (int d = 0; d < DD; d++)
                    if (e[d] >= 0) s += atoms[((size_t)(bidx * MM + e[d])) * FA + f];
            } else {
                const float* bq = bonds + (size_t)(row0 + r) * DD * FB + (f - FA);
                #pragma unroll
                for (int d = 0; d < DD; d++) s += bq[d * FB];
            }
            sfp[f] = s;
        }
        __syncwarp();
        const float4* bi4 = reinterpret_cast<const float4*>(b_inner) + dg * 32 + lane;
        const float4* w4  = reinterpret_cast<const float4*>(W_inner) + ((size_t)dg * FAN) * 32 + lane;
        float4 z = __ldg(bi4);
        #pragma unroll
        for (int f = 0; f < FAN; f++) {
            float  s = sfp[f];
            float4 w = __ldg(w4 + (size_t)f * 32);
            z.x = fmaf(s, w.x, z.x);
            z.y = fmaf(s, w.y, z.y);
            z.z = fmaf(s, w.z, z.z);
            z.w = fmaf(s, w.w, z.w);
        }
        float4* op = reinterpret_cast<float4*>(out + (size_t)(row0 + r) * CC) + lane;
        float4 cur = *op;
        cur.x += fmaxf(z.x, 0.f);
        cur.y += fmaxf(z.y, 0.f);
        cur.z += fmaxf(z.z, 0.f);
        cur.w += fmaxf(z.w, 0.f);
        *op = cur;
        __syncwarp();
    }
}

extern "C" void kernel_launch(void* const* d_in, const int* in_sizes, int n_in,
                              void* d_out, int out_size) {
    const float* atoms   = (const float*)d_in[0];
    const float* bonds   = (const float*)d_in[1];
    const int*   edges   = (const int*)  d_in[2];
    const float* W_inner = (const float*)d_in[3];
    const float* b_inner = (const float*)d_in[4];
    const float* W_self  = (const float*)d_in[5];
    const float* b_self  = (const float*)d_in[6];
    float* out = (float*)d_out;

    cudaFuncSetAttribute(tga_kernel, cudaFuncAttributeMaxDynamicSharedMemorySize, SM_TOTAL);
    tga_kernel<<<BB, NTHR, SM_TOTAL>>>(atoms, bonds, edges,
                                       W_inner, b_inner, W_self, b_self, out);
}

// round 8
// speedup vs baseline: 2.3218x; 1.2102x over previous
#include <cuda_runtime.h>
#include <cuda_bf16.h>
#include <cstdint>

// Problem constants
#define BB   2048
#define MM   128
#define FA   62
#define FB   6
#define DD   5
#define CC   128
#define FAN  68
#define NTHR 256
#define KP   80            // K padded to 5 mma-steps of 16
#define STRD 88            // smem row stride in bf16 (176 B -> ldmatrix conflict-free)

// SMEM byte offsets
#define SM_AHI   0                       // 128 x 88 bf16 = 22528
#define SM_ALO   22528
#define SM_BHI   45056                   // 128n x 88k bf16
#define SM_BLO   67584
#define SM_BSELF 90112                   // float[128]
#define SM_SFW   90624                   // 8 warps * 72 floats
#define SM_RARE  92928                   // int[128]
#define SM_NRARE 93440
#define SM_TOTAL 93568

__device__ __forceinline__ uint32_t smem_to_u32(const void* p) {
    uint32_t a;
    asm("{ .reg .u64 t; cvta.to.shared.u64 t, %1; cvt.u32.u64 %0, t; }" : "=r"(a) : "l"(p));
    return a;
}
__device__ __forceinline__ void ldsm_x4(uint32_t* r, uint32_t addr) {
    asm volatile("ldmatrix.sync.aligned.m8n8.x4.shared.b16 {%0,%1,%2,%3}, [%4];"
                 : "=r"(r[0]), "=r"(r[1]), "=r"(r[2]), "=r"(r[3]) : "r"(addr));
}
__device__ __forceinline__ void mma_bf16(float* d, const uint32_t* a, const uint32_t* b) {
    asm volatile("mma.sync.aligned.m16n8k16.row.col.f32.bf16.bf16.f32 "
                 "{%0,%1,%2,%3}, {%4,%5,%6,%7}, {%8,%9}, {%0,%1,%2,%3};"
                 : "+f"(d[0]), "+f"(d[1]), "+f"(d[2]), "+f"(d[3])
                 : "r"(a[0]), "r"(a[1]), "r"(a[2]), "r"(a[3]), "r"(b[0]), "r"(b[1]));
}
// fp32 pair -> packed bf16x2 hi and lo (x = hi + lo to ~2^-18 relative)
__device__ __forceinline__ void split2(float x0, float x1, uint32_t& hi, uint32_t& lo) {
    __nv_bfloat162 h = __floats2bfloat162_rn(x0, x1);
    float h0 = __bfloat162float(__low2bfloat16(h));
    float h1 = __bfloat162float(__high2bfloat16(h));
    __nv_bfloat162 l = __floats2bfloat162_rn(x0 - h0, x1 - h1);
    hi = *reinterpret_cast<uint32_t*>(&h);
    lo = *reinterpret_cast<uint32_t*>(&l);
}

__global__ __launch_bounds__(NTHR, 2)
void tga_kernel(const float* __restrict__ atoms,
                const float* __restrict__ bonds,
                const int*   __restrict__ edges,
                const float* __restrict__ W_inner,
                const float* __restrict__ b_inner,
                const float* __restrict__ W_self,
                const float* __restrict__ b_self,
                float* __restrict__ out) {
    extern __shared__ char smem[];
    const uint32_t smem_base = smem_to_u32(smem);
    const int tid  = threadIdx.x;
    const int lane = tid & 31;
    const int warp = tid >> 5;
    const int row0 = blockIdx.x * MM;      // one batch per CTA
    const int bidx = blockIdx.x;

    if (tid == 0) *reinterpret_cast<int*>(smem + SM_NRARE) = 0;
    __syncthreads();

    // ---------------- Stage A: atoms, fully coalesced -----------------------
    // atoms rows are 62 floats = 31 float2, rows contiguous -> linear float2 array.
    {
        const float2* a2 = reinterpret_cast<const float2*>(atoms + (size_t)row0 * FA);
        #pragma unroll
        for (int idx = tid; idx < MM * 31; idx += NTHR) {
            int r = idx / 31, j = idx % 31;          // f = 2j, 2j+1
            float2 v = a2[idx];                       // lane-consecutive: coalesced
            uint32_t hi, lo;
            split2(v.x, v.y, hi, lo);
            *reinterpret_cast<uint32_t*>(smem + SM_AHI + r * (STRD*2) + 4*j) = hi;
            *reinterpret_cast<uint32_t*>(smem + SM_ALO + r * (STRD*2) + 4*j) = lo;
        }
    }
    // summed bonds -> k 62..67, zeros -> k 68..79 (one thread per row; each row's
    // 30 bond floats are contiguous, consumed whole -> acceptable traffic)
    if (tid < MM) {
        char* ah = smem + SM_AHI + tid * (STRD*2);
        char* al = smem + SM_ALO + tid * (STRD*2);
        float bs[FB];
        #pragma unroll
        for (int f = 0; f < FB; f++) bs[f] = 0.f;
        const float2* bp = reinterpret_cast<const float2*>(bonds + (size_t)(row0 + tid) * DD * FB);
        #pragma unroll
        for (int p = 0; p < 15; p++) {
            float2 v = bp[p];
            int f0 = (2*p) % FB, f1 = (2*p + 1) % FB;
            bs[f0] += v.x;
            bs[f1] += v.y;
        }
        #pragma unroll
        for (int p = 0; p < 3; p++) {
            uint32_t hi, lo;
            split2(bs[2*p], bs[2*p + 1], hi, lo);
            *reinterpret_cast<uint32_t*>(ah + 4*(31 + p)) = hi;
            *reinterpret_cast<uint32_t*>(al + 4*(31 + p)) = lo;
        }
        #pragma unroll
        for (int j = 34; j < 40; j++) {              // k pad 68..79
            *reinterpret_cast<uint32_t*>(ah + 4*j) = 0u;
            *reinterpret_cast<uint32_t*>(al + 4*j) = 0u;
        }
    }

    // ---------------- Stage B = W_self^T as bf16 hi/lo  ([n][k], k-contig) ----
    for (int idx = tid; idx < FAN * CC; idx += NTHR) {
        int k = idx >> 7, n = idx & (CC - 1);       // coalesced LDG over n
        float w = W_self[idx];
        __nv_bfloat16 h = __float2bfloat16(w);
        __nv_bfloat16 l = __float2bfloat16(w - __bfloat162float(h));
        uint32_t off = (uint32_t)n * (STRD * 2) + (uint32_t)k * 2;
        *reinterpret_cast<__nv_bfloat16*>(smem + SM_BHI + off) = h;
        *reinterpret_cast<__nv_bfloat16*>(smem + SM_BLO + off) = l;
    }
    for (int idx = tid; idx < (KP - FAN) * CC; idx += NTHR) {   // k pad 68..79
        int k = FAN + (idx >> 7), n = idx & (CC - 1);
        uint32_t off = (uint32_t)n * (STRD * 2) + (uint32_t)k * 2;
        *reinterpret_cast<__nv_bfloat16*>(smem + SM_BHI + off) = __nv_bfloat16(0.f);
        *reinterpret_cast<__nv_bfloat16*>(smem + SM_BLO + off) = __nv_bfloat16(0.f);
    }

    // bias, degree + rare list
    if (tid < CC) reinterpret_cast<float*>(smem + SM_BSELF)[tid] = b_self[tid];
    if (tid >= CC && tid < CC + MM) {
        const int r = tid - CC;
        const int* ep = edges + (size_t)(row0 + r) * DD;
        int dg = 0;
        #pragma unroll
        for (int d = 0; d < DD; d++) dg += (ep[d] >= 0);
        if (dg < DD) {
            int p = atomicAdd(reinterpret_cast<int*>(smem + SM_NRARE), 1);
            reinterpret_cast<int*>(smem + SM_RARE)[p] = r | (dg << 8);
        }
    }
    __syncthreads();

    // ---------------- Tensor-core GEMM: D = Ah*Bh + Ah*Bl + Al*Bh -------------
    // warp tile: m32 x n64.  warp grid: 4 m-groups x 2 n-halves.
    // Each B ldmatrix.x4 now feeds FOUR mmas (2 m-frags x 2 n8) -> B-LDSM halved.
    const int wm = (warp & 3) * 32;
    const int wn = (warp >> 2) * 64;

    float acc0[8][4], acc1[8][4];
    #pragma unroll
    for (int j = 0; j < 8; j++)
        #pragma unroll
        for (int q = 0; q < 4; q++) { acc0[j][q] = 0.f; acc1[j][q] = 0.f; }

    const uint32_t arow0 = ((uint32_t)(wm + (lane & 15)) * STRD + ((lane >> 4) << 3)) * 2;
    const uint32_t arow1 = arow0 + 16 * (STRD * 2);
    const uint32_t brow  = ((uint32_t)(wn + (lane & 7) + ((lane & 16) >> 1)) * STRD) * 2
                         + (lane & 8) * 2;

    #pragma unroll 1
    for (int term = 0; term < 3; term++) {
        const uint32_t abase = smem_base + (term == 2 ? SM_ALO : SM_AHI);
        const uint32_t bbase = smem_base + (term == 1 ? SM_BLO : SM_BHI) + brow;
        #pragma unroll
        for (int kk = 0; kk < 5; kk++) {
            uint32_t a0[4], a1[4];
            ldsm_x4(a0, abase + arow0 + kk * 32);
            ldsm_x4(a1, abase + arow1 + kk * 32);
            #pragma unroll
            for (int jp = 0; jp < 4; jp++) {
                uint32_t b[4];
                ldsm_x4(b, bbase + (uint32_t)jp * 16 * (STRD * 2) + kk * 32);
                mma_bf16(acc0[2*jp],     a0, b);
                mma_bf16(acc0[2*jp + 1], a0, b + 2);
                mma_bf16(acc1[2*jp],     a1, b);
                mma_bf16(acc1[2*jp + 1], a1, b + 2);
            }
        }
    }

    // ---------------- Epilogue: bias + relu + STG.64 --------------------------
    {
        const float* bs = reinterpret_cast<const float*>(smem + SM_BSELF);
        const int rb  = wm + (lane >> 2);
        const int c00 = wn + 2 * (lane & 3);
        #pragma unroll
        for (int mi = 0; mi < 2; mi++) {
            const int rr = rb + 16 * mi;
            float* orow0 = out + (size_t)(row0 + rr) * CC;
            float* orow1 = out + (size_t)(row0 + rr + 8) * CC;
            #pragma unroll
            for (int j = 0; j < 8; j++) {
                const float (*av)[4] = mi ? acc1 : acc0;
                int c = c00 + 8 * j;
                float b0 = bs[c], b1 = bs[c + 1];
                float2 v0, v1;
                v0.x = fmaxf(av[j][0] + b0, 0.f);
                v0.y = fmaxf(av[j][1] + b1, 0.f);
                v1.x = fmaxf(av[j][2] + b0, 0.f);
                v1.y = fmaxf(av[j][3] + b1, 0.f);
                *reinterpret_cast<float2*>(orow0 + c) = v0;
                *reinterpret_cast<float2*>(orow1 + c) = v1;
            }
        }
    }
    __syncthreads();   // order epilogue STGs before rare-row RMW (same CTA/SM)

    // ---------------- Rare rows (deg<5, ~3.8%): warp-parallel zni patch -------
    const int nr = *reinterpret_cast<int*>(smem + SM_NRARE);
    float* sfp = reinterpret_cast<float*>(smem + SM_SFW) + warp * 72;
    for (int i = warp; i < nr; i += 8) {
        int packed = reinterpret_cast<int*>(smem + SM_RARE)[i];
        int r  = packed & 0xFF;
        int dg = packed >> 8;
        int e[DD];
        #pragma unroll
        for (int d = 0; d < DD; d++) e[d] = edges[(size_t)(row0 + r) * DD + d];
        #pragma unroll
        for (int f = lane; f < FAN; f += 32) {
            float s = 0.f;
            if (f < FA) {
                #pragma unroll
                for (int d = 0; d < DD; d++)
                    if (e[d] >= 0) s += atoms[((size_t)(bidx * MM + e[d])) * FA + f];
            } else {
                const float* bq = bonds + (size_t)(row0 + r) * DD * FB + (f - FA);
                #pragma unroll
                for (int d = 0; d < DD; d++) s += bq[d * FB];
            }
            sfp[f] = s;
        }
        __syncwarp();
        const float4* bi4 = reinterpret_cast<const float4*>(b_inner) + dg * 32 + lane;
        const float4* w4  = reinterpret_cast<const float4*>(W_inner) + ((size_t)dg * FAN) * 32 + lane;
        float4 z = __ldg(bi4);
        #pragma unroll
        for (int f = 0; f < FAN; f++) {
            float  s = sfp[f];
            float4 w = __ldg(w4 + (size_t)f * 32);
            z.x = fmaf(s, w.x, z.x);
            z.y = fmaf(s, w.y, z.y);
            z.z = fmaf(s, w.z, z.z);
            z.w = fmaf(s, w.w, z.w);
        }
        float4* op = reinterpret_cast<float4*>(out + (size_t)(row0 + r) * CC) + lane;
        float4 cur = *op;
        cur.x += fmaxf(z.x, 0.f);
        cur.y += fmaxf(z.y, 0.f);
        cur.z += fmaxf(z.z, 0.f);
        cur.w += fmaxf(z.w, 0.f);
        *op = cur;
        __syncwarp();
    }
}

extern "C" void kernel_launch(void* const* d_in, const int* in_sizes, int n_in,
                              void* d_out, int out_size) {
    const float* atoms   = (const float*)d_in[0];
    const float* bonds   = (const float*)d_in[1];
    const int*   edges   = (const int*)  d_in[2];
    const float* W_inner = (const float*)d_in[3];
    const float* b_inner = (const float*)d_in[4];
    const float* W_self  = (const float*)d_in[5];
    const float* b_self  = (const float*)d_in[6];
    float* out = (float*)d_out;

    cudaFuncSetAttribute(tga_kernel, cudaFuncAttributeMaxDynamicSharedMemorySize, SM_TOTAL);
    tga_kernel<<<BB, NTHR, SM_TOTAL>>>(atoms, bonds, edges,
                                       W_inner, b_inner, W_self, b_self, out);
}

// round 10
// speedup vs baseline: 2.6444x; 1.1390x over previous
#include <cuda_runtime.h>
#include <cuda_bf16.h>
#include <cstdint>

// Problem constants
#define BB   2048
#define MM   128
#define FA   62
#define FB   6
#define DD   5
#define CC   128
#define FAN  68
#define NTHR 256
#define KP   80            // K padded to 5 mma-steps of 16
#define STRD 88            // smem row stride in bf16 (176 B -> ldmatrix conflict-free)

// SMEM byte offsets (BHI/BLO contiguous: copied as one 45056-B image)
#define SM_AHI   0                       // 128 x 88 bf16 = 22528
#define SM_ALO   22528
#define SM_BHI   45056
#define SM_BLO   67584
#define SM_BSELF 90112                   // float[128]
#define SM_SFW   90624                   // 8 warps * 72 floats
#define SM_RARE  92928                   // int[128]
#define SM_NRARE 93440
#define SM_TOTAL 93568

#define BTILE_BYTES 45056
// Pre-split W_self image (bf16 hi | lo), exact smem layout, built once per launch.
__device__ __align__(16) unsigned char g_btile[BTILE_BYTES];

__device__ __forceinline__ uint32_t smem_to_u32(const void* p) {
    uint32_t a;
    asm("{ .reg .u64 t; cvta.to.shared.u64 t, %1; cvt.u32.u64 %0, t; }" : "=r"(a) : "l"(p));
    return a;
}
__device__ __forceinline__ void ldsm_x4(uint32_t* r, uint32_t addr) {
    asm volatile("ldmatrix.sync.aligned.m8n8.x4.shared.b16 {%0,%1,%2,%3}, [%4];"
                 : "=r"(r[0]), "=r"(r[1]), "=r"(r[2]), "=r"(r[3]) : "r"(addr));
}
__device__ __forceinline__ void mma_bf16(float* d, const uint32_t* a, const uint32_t* b) {
    asm volatile("mma.sync.aligned.m16n8k16.row.col.f32.bf16.bf16.f32 "
                 "{%0,%1,%2,%3}, {%4,%5,%6,%7}, {%8,%9}, {%0,%1,%2,%3};"
                 : "+f"(d[0]), "+f"(d[1]), "+f"(d[2]), "+f"(d[3])
                 : "r"(a[0]), "r"(a[1]), "r"(a[2]), "r"(a[3]), "r"(b[0]), "r"(b[1]));
}
// fp32 pair -> packed bf16x2 hi and lo (x = hi + lo to ~2^-18 relative)
__device__ __forceinline__ void split2(float x0, float x1, uint32_t& hi, uint32_t& lo) {
    __nv_bfloat162 h = __floats2bfloat162_rn(x0, x1);
    float h0 = __bfloat162float(__low2bfloat16(h));
    float h1 = __bfloat162float(__high2bfloat16(h));
    __nv_bfloat162 l = __floats2bfloat162_rn(x0 - h0, x1 - h1);
    hi = *reinterpret_cast<uint32_t*>(&h);
    lo = *reinterpret_cast<uint32_t*>(&l);
}

// ---------------- Prep: W_self -> bf16 hi/lo padded image ------------------
__global__ void prep_kernel(const float* __restrict__ W_self) {
    const int k = blockIdx.x;        // 0..KP-1
    const int n = threadIdx.x;       // 0..127
    __nv_bfloat16 h = __float2bfloat16(0.f), l = h;
    if (k < FAN) {
        float w = W_self[(size_t)k * CC + n];
        h = __float2bfloat16(w);
        l = __float2bfloat16(w - __bfloat162float(h));
    }
    const uint32_t off = (uint32_t)n * (STRD * 2) + (uint32_t)k * 2;
    *reinterpret_cast<__nv_bfloat16*>(g_btile + off)                      = h;  // BHI
    *reinterpret_cast<__nv_bfloat16*>(g_btile + (SM_BLO - SM_BHI) + off)  = l;  // BLO
}

__global__ __launch_bounds__(NTHR, 2)
void tga_kernel(const float* __restrict__ atoms,
                const float* __restrict__ bonds,
                const int*   __restrict__ edges,
                const float* __restrict__ W_inner,
                const float* __restrict__ b_inner,
                const float* __restrict__ b_self,
                float* __restrict__ out) {
    extern __shared__ char smem[];
    const uint32_t smem_base = smem_to_u32(smem);
    const int tid  = threadIdx.x;
    const int lane = tid & 31;
    const int warp = tid >> 5;
    const int row0 = blockIdx.x * MM;      // one batch per CTA
    const int bidx = blockIdx.x;

    if (tid == 0) *reinterpret_cast<int*>(smem + SM_NRARE) = 0;
    __syncthreads();

    // ---------------- Stage B: straight float4 copy of the prebuilt image ----
    {
        const float4* src = reinterpret_cast<const float4*>(g_btile);
        float4* dst = reinterpret_cast<float4*>(smem + SM_BHI);
        #pragma unroll
        for (int i = tid; i < BTILE_BYTES / 16; i += NTHR) dst[i] = src[i];
    }

    // ---------------- Stage A: atoms, fully coalesced -----------------------
    {
        const float2* a2 = reinterpret_cast<const float2*>(atoms + (size_t)row0 * FA);
        #pragma unroll
        for (int idx = tid; idx < MM * 31; idx += NTHR) {
            int r = idx / 31, j = idx % 31;          // f = 2j, 2j+1
            float2 v = a2[idx];                       // lane-consecutive: coalesced
            uint32_t hi, lo;
            split2(v.x, v.y, hi, lo);
            *reinterpret_cast<uint32_t*>(smem + SM_AHI + r * (STRD*2) + 4*j) = hi;
            *reinterpret_cast<uint32_t*>(smem + SM_ALO + r * (STRD*2) + 4*j) = lo;
        }
    }
    // summed bonds -> k 62..67, zeros -> k 68..79 (one thread per row)
    if (tid < MM) {
        char* ah = smem + SM_AHI + tid * (STRD*2);
        char* al = smem + SM_ALO + tid * (STRD*2);
        float bs[FB];
        #pragma unroll
        for (int f = 0; f < FB; f++) bs[f] = 0.f;
        const float2* bp = reinterpret_cast<const float2*>(bonds + (size_t)(row0 + tid) * DD * FB);
        #pragma unroll
        for (int p = 0; p < 15; p++) {
            float2 v = bp[p];
            int f0 = (2*p) % FB, f1 = (2*p + 1) % FB;
            bs[f0] += v.x;
            bs[f1] += v.y;
        }
        #pragma unroll
        for (int p = 0; p < 3; p++) {
            uint32_t hi, lo;
            split2(bs[2*p], bs[2*p + 1], hi, lo);
            *reinterpret_cast<uint32_t*>(ah + 4*(31 + p)) = hi;
            *reinterpret_cast<uint32_t*>(al + 4*(31 + p)) = lo;
        }
        #pragma unroll
        for (int j = 34; j < 40; j++) {              // k pad 68..79
            *reinterpret_cast<uint32_t*>(ah + 4*j) = 0u;
            *reinterpret_cast<uint32_t*>(al + 4*j) = 0u;
        }
    }

    // bias, degree + rare list
    if (tid < CC) reinterpret_cast<float*>(smem + SM_BSELF)[tid] = b_self[tid];
    if (tid >= CC && tid < CC + MM) {
        const int r = tid - CC;
        const int* ep = edges + (size_t)(row0 + r) * DD;
        int dg = 0;
        #pragma unroll
        for (int d = 0; d < DD; d++) dg += (ep[d] >= 0);
        if (dg < DD) {
            int p = atomicAdd(reinterpret_cast<int*>(smem + SM_NRARE), 1);
            reinterpret_cast<int*>(smem + SM_RARE)[p] = r | (dg << 8);
        }
    }
    __syncthreads();

    // ---------------- Tensor-core GEMM: D = Ah*Bh + Ah*Bl + Al*Bh -------------
    // warp tile m32 x n64; term-fused: A frags loaded once per kk, B frags once
    // per (kk, jp); each (kk, jp) issues all 12 MMAs. ldsm/warp: 90 -> 60.
    const int wm = (warp & 3) * 32;
    const int wn = (warp >> 2) * 64;

    float acc0[8][4], acc1[8][4];
    #pragma unroll
    for (int j = 0; j < 8; j++)
        #pragma unroll
        for (int q = 0; q < 4; q++) { acc0[j][q] = 0.f; acc1[j][q] = 0.f; }

    const uint32_t arow0 = ((uint32_t)(wm + (lane & 15)) * STRD + ((lane >> 4) << 3)) * 2;
    const uint32_t arow1 = arow0 + 16 * (STRD * 2);
    const uint32_t brow  = ((uint32_t)(wn + (lane & 7) + ((lane & 16) >> 1)) * STRD) * 2
                         + (lane & 8) * 2;

    #pragma unroll
    for (int kk = 0; kk < 5; kk++) {
        uint32_t ah0[4], ah1[4], al0[4], al1[4];
        ldsm_x4(ah0, smem_base + SM_AHI + arow0 + kk * 32);
        ldsm_x4(ah1, smem_base + SM_AHI + arow1 + kk * 32);
        ldsm_x4(al0, smem_base + SM_ALO + arow0 + kk * 32);
        ldsm_x4(al1, smem_base + SM_ALO + arow1 + kk * 32);
        #pragma unroll
        for (int jp = 0; jp < 4; jp++) {
            uint32_t bh[4], bl[4];
            ldsm_x4(bh, smem_base + SM_BHI + brow + (uint32_t)jp * 16 * (STRD * 2) + kk * 32);
            ldsm_x4(bl, smem_base + SM_BLO + brow + (uint32_t)jp * 16 * (STRD * 2) + kk * 32);
            mma_bf16(acc0[2*jp],     ah0, bh);
            mma_bf16(acc0[2*jp + 1], ah0, bh + 2);
            mma_bf16(acc1[2*jp],     ah1, bh);
            mma_bf16(acc1[2*jp + 1], ah1, bh + 2);
            mma_bf16(acc0[2*jp],     ah0, bl);
            mma_bf16(acc0[2*jp + 1], ah0, bl + 2);
            mma_bf16(acc1[2*jp],     ah1, bl);
            mma_bf16(acc1[2*jp + 1], ah1, bl + 2);
            mma_bf16(acc0[2*jp],     al0, bh);
            mma_bf16(acc0[2*jp + 1], al0, bh + 2);
            mma_bf16(acc1[2*jp],     al1, bh);
            mma_bf16(acc1[2*jp + 1], al1, bh + 2);
        }
    }

    // ---------------- Epilogue: bias + relu + STG.64 --------------------------
    {
        const float* bs = reinterpret_cast<const float*>(smem + SM_BSELF);
        const int rb  = wm + (lane >> 2);
        const int c00 = wn + 2 * (lane & 3);
        #pragma unroll
        for (int mi = 0; mi < 2; mi++) {
            const int rr = rb + 16 * mi;
            float* orow0 = out + (size_t)(row0 + rr) * CC;
            float* orow1 = out + (size_t)(row0 + rr + 8) * CC;
            #pragma unroll
            for (int j = 0; j < 8; j++) {
                const float (*av)[4] = mi ? acc1 : acc0;
                int c = c00 + 8 * j;
                float b0 = bs[c], b1 = bs[c + 1];
                float2 v0, v1;
                v0.x = fmaxf(av[j][0] + b0, 0.f);
                v0.y = fmaxf(av[j][1] + b1, 0.f);
                v1.x = fmaxf(av[j][2] + b0, 0.f);
                v1.y = fmaxf(av[j][3] + b1, 0.f);
                *reinterpret_cast<float2*>(orow0 + c) = v0;
                *reinterpret_cast<float2*>(orow1 + c) = v1;
            }
        }
    }
    __syncthreads();   // order epilogue STGs before rare-row RMW (same CTA/SM)

    // ---------------- Rare rows (deg<5, ~3.8%): warp-parallel zni patch -------
    const int nr = *reinterpret_cast<int*>(smem + SM_NRARE);
    float* sfp = reinterpret_cast<float*>(smem + SM_SFW) + warp * 72;
    for (int i = warp; i < nr; i += 8) {
        int packed = reinterpret_cast<int*>(smem + SM_RARE)[i];
        int r  = packed & 0xFF;
        int dg = packed >> 8;
        int e[DD];
        #pragma unroll
        for (int d = 0; d < DD; d++) e[d] = edges[(size_t)(row0 + r) * DD + d];
        #pragma unroll
        for (int f = lane; f < FAN; f += 32) {
            float s = 0.f;
            if (f < FA) {
                #pragma unroll
                for (int d = 0; d < DD; d++)
                    if (e[d] >= 0) s += atoms[((size_t)(bidx * MM + e[d])) * FA + f];
            } else {
                const float* bq = bonds + (size_t)(row0 + r) * DD * FB + (f - FA);
                #pragma unroll
                for (int d = 0; d < DD; d++) s += bq[d * FB];
            }
            sfp[f] = s;
        }
        __syncwarp();
        const float4* bi4 = reinterpret_cast<const float4*>(b_inner) + dg * 32 + lane;
        const float4* w4  = reinterpret_cast<const float4*>(W_inner) + ((size_t)dg * FAN) * 32 + lane;
        float4 z = __ldg(bi4);
        #pragma unroll
        for (int f = 0; f < FAN; f++) {
            float  s = sfp[f];
            float4 w = __ldg(w4 + (size_t)f * 32);
            z.x = fmaf(s, w.x, z.x);
            z.y = fmaf(s, w.y, z.y);
            z.z = fmaf(s, w.z, z.z);
            z.w = fmaf(s, w.w, z.w);
        }
        float4* op = reinterpret_cast<float4*>(out + (size_t)(row0 + r) * CC) + lane;
        float4 cur = *op;
        cur.x += fmaxf(z.x, 0.f);
        cur.y += fmaxf(z.y, 0.f);
        cur.z += fmaxf(z.z, 0.f);
        cur.w += fmaxf(z.w, 0.f);
        *op = cur;
        __syncwarp();
    }
}

extern "C" void kernel_launch(void* const* d_in, const int* in_sizes, int n_in,
                              void* d_out, int out_size) {
    const float* atoms   = (const float*)d_in[0];
    const float* bonds   = (const float*)d_in[1];
    const int*   edges   = (const int*)  d_in[2];
    const float* W_inner = (const float*)d_in[3];
    const float* b_inner = (const float*)d_in[4];
    const float* W_self  = (const float*)d_in[5];
    const float* b_self  = (const float*)d_in[6];
    float* out = (float*)d_out;

    prep_kernel<<<KP, CC>>>(W_self);

    cudaFuncSetAttribute(tga_kernel, cudaFuncAttributeMaxDynamicSharedMemorySize, SM_TOTAL);
    tga_kernel<<<BB, NTHR, SM_TOTAL>>>(atoms, bonds, edges,
                                       W_inner, b_inner, b_self, out);
}

// round 11
// speedup vs baseline: 2.7425x; 1.0371x over previous
#include <cuda_runtime.h>
#include <cuda_bf16.h>
#include <cstdint>

// Problem constants
#define BB   2048
#define MM   128
#define FA   62
#define FB   6
#define DD   5
#define CC   128
#define FAN  68
#define NTHR 256
#define KP   80            // K padded to 5 mma-steps of 16
#define STRD 88            // smem row stride in bf16 (176 B -> ldmatrix conflict-free)

// SMEM byte offsets (BHI/BLO contiguous: copied as one 45056-B image)
#define SM_AHI   0                       // 128 x 88 bf16 = 22528
#define SM_ALO   22528
#define SM_BHI   45056                   // also reused as raw-bonds staging (15360 B)
#define SM_BLO   67584
#define SM_BSELF 90112                   // float[128]
#define SM_SFW   90624                   // 8 warps * 72 floats
#define SM_RARE  92928                   // int[128]
#define SM_NRARE 93440
#define SM_BSUM  93444                   // float[128*6] fp32 bond sums (tail reuse)
#define SM_TOTAL 96528

#define BTILE_BYTES 45056
// Pre-split W_self image (bf16 hi | lo), exact smem layout, built once per launch.
__device__ __align__(16) unsigned char g_btile[BTILE_BYTES];

__device__ __forceinline__ uint32_t smem_to_u32(const void* p) {
    uint32_t a;
    asm("{ .reg .u64 t; cvta.to.shared.u64 t, %1; cvt.u32.u64 %0, t; }" : "=r"(a) : "l"(p));
    return a;
}
__device__ __forceinline__ void ldsm_x4(uint32_t* r, uint32_t addr) {
    asm volatile("ldmatrix.sync.aligned.m8n8.x4.shared.b16 {%0,%1,%2,%3}, [%4];"
                 : "=r"(r[0]), "=r"(r[1]), "=r"(r[2]), "=r"(r[3]) : "r"(addr));
}
__device__ __forceinline__ void mma_bf16(float* d, const uint32_t* a, const uint32_t* b) {
    asm volatile("mma.sync.aligned.m16n8k16.row.col.f32.bf16.bf16.f32 "
                 "{%0,%1,%2,%3}, {%4,%5,%6,%7}, {%8,%9}, {%0,%1,%2,%3};"
                 : "+f"(d[0]), "+f"(d[1]), "+f"(d[2]), "+f"(d[3])
                 : "r"(a[0]), "r"(a[1]), "r"(a[2]), "r"(a[3]), "r"(b[0]), "r"(b[1]));
}
// fp32 pair -> packed bf16x2 hi and lo (x = hi + lo to ~2^-18 relative)
__device__ __forceinline__ void split2(float x0, float x1, uint32_t& hi, uint32_t& lo) {
    __nv_bfloat162 h = __floats2bfloat162_rn(x0, x1);
    float h0 = __bfloat162float(__low2bfloat16(h));
    float h1 = __bfloat162float(__high2bfloat16(h));
    __nv_bfloat162 l = __floats2bfloat162_rn(x0 - h0, x1 - h1);
    hi = *reinterpret_cast<uint32_t*>(&h);
    lo = *reinterpret_cast<uint32_t*>(&l);
}

// ---------------- Prep: W_self -> bf16 hi/lo padded image ------------------
__global__ void prep_kernel(const float* __restrict__ W_self) {
    const int k = blockIdx.x;        // 0..KP-1
    const int n = threadIdx.x;       // 0..127
    __nv_bfloat16 h = __float2bfloat16(0.f), l = h;
    if (k < FAN) {
        float w = W_self[(size_t)k * CC + n];
        h = __float2bfloat16(w);
        l = __float2bfloat16(w - __bfloat162float(h));
    }
    const uint32_t off = (uint32_t)n * (STRD * 2) + (uint32_t)k * 2;
    *reinterpret_cast<__nv_bfloat16*>(g_btile + off)                      = h;  // BHI
    *reinterpret_cast<__nv_bfloat16*>(g_btile + (SM_BLO - SM_BHI) + off)  = l;  // BLO
    // PDL: allow the dependent main kernel to start its independent staging.
    asm volatile("griddepcontrol.launch_dependents;");
}

__global__ __launch_bounds__(NTHR, 2)
void tga_kernel(const float* __restrict__ atoms,
                const float* __restrict__ bonds,
                const int*   __restrict__ edges,
                const float* __restrict__ W_inner,
                const float* __restrict__ b_inner,
                const float* __restrict__ b_self,
                float* __restrict__ out) {
    extern __shared__ char smem[];
    const uint32_t smem_base = smem_to_u32(smem);
    const int tid  = threadIdx.x;
    const int lane = tid & 31;
    const int warp = tid >> 5;
    const int row0 = blockIdx.x * MM;      // one batch per CTA
    const int bidx = blockIdx.x;

    if (tid == 0) *reinterpret_cast<int*>(smem + SM_NRARE) = 0;
    __syncthreads();

    // ---------------- Phase 1: coalesced global staging ---------------------
    // raw bonds (15360 B) -> SM_BHI region (B image not needed yet), float4 linear
    {
        const float4* src = reinterpret_cast<const float4*>(bonds + (size_t)row0 * DD * FB);
        float4* dst = reinterpret_cast<float4*>(smem + SM_BHI);
        #pragma unroll
        for (int i = tid; i < MM * DD * FB / 4; i += NTHR) dst[i] = src[i];
    }
    // atoms -> A tiles k 0..61, fully coalesced
    {
        const float2* a2 = reinterpret_cast<const float2*>(atoms + (size_t)row0 * FA);
        #pragma unroll
        for (int idx = tid; idx < MM * 31; idx += NTHR) {
            int r = idx / 31, j = idx % 31;          // f = 2j, 2j+1
            float2 v = a2[idx];                       // lane-consecutive: coalesced
            uint32_t hi, lo;
            split2(v.x, v.y, hi, lo);
            *reinterpret_cast<uint32_t*>(smem + SM_AHI + r * (STRD*2) + 4*j) = hi;
            *reinterpret_cast<uint32_t*>(smem + SM_ALO + r * (STRD*2) + 4*j) = lo;
        }
    }
    // bias, degree + rare list
    if (tid < CC) reinterpret_cast<float*>(smem + SM_BSELF)[tid] = b_self[tid];
    if (tid >= CC && tid < CC + MM) {
        const int r = tid - CC;
        const int* ep = edges + (size_t)(row0 + r) * DD;
        int dg = 0;
        #pragma unroll
        for (int d = 0; d < DD; d++) dg += (ep[d] >= 0);
        if (dg < DD) {
            int p = atomicAdd(reinterpret_cast<int*>(smem + SM_NRARE), 1);
            reinterpret_cast<int*>(smem + SM_RARE)[p] = r | (dg << 8);
        }
    }
    __syncthreads();

    // ---------------- Phase 2: bond sums from smem ---------------------------
    if (tid < MM) {
        const float* bb = reinterpret_cast<const float*>(smem + SM_BHI) + tid * (DD * FB);
        float bs[FB];
        #pragma unroll
        for (int f = 0; f < FB; f++) bs[f] = 0.f;
        #pragma unroll
        for (int d = 0; d < DD; d++)
            #pragma unroll
            for (int f = 0; f < FB; f++) bs[f] += bb[d * FB + f];
        // fp32 sums for the rare tail
        float* bsum = reinterpret_cast<float*>(smem + SM_BSUM) + tid * FB;
        #pragma unroll
        for (int f = 0; f < FB; f++) bsum[f] = bs[f];
        // bf16 hi/lo -> A tiles k 62..67, zeros k 68..79
        char* ah = smem + SM_AHI + tid * (STRD*2);
        char* al = smem + SM_ALO + tid * (STRD*2);
        #pragma unroll
        for (int p = 0; p < 3; p++) {
            uint32_t hi, lo;
            split2(bs[2*p], bs[2*p + 1], hi, lo);
            *reinterpret_cast<uint32_t*>(ah + 4*(31 + p)) = hi;
            *reinterpret_cast<uint32_t*>(al + 4*(31 + p)) = lo;
        }
        #pragma unroll
        for (int j = 34; j < 40; j++) {
            *reinterpret_cast<uint32_t*>(ah + 4*j) = 0u;
            *reinterpret_cast<uint32_t*>(al + 4*j) = 0u;
        }
    }
    __syncthreads();        // raw-bonds region free; B copy may overwrite

    // ---------------- Phase 3: B image copy (after prep completes, via PDL) --
    asm volatile("griddepcontrol.wait;" ::: "memory");
    {
        const float4* src = reinterpret_cast<const float4*>(g_btile);
        float4* dst = reinterpret_cast<float4*>(smem + SM_BHI);
        #pragma unroll
        for (int i = tid; i < BTILE_BYTES / 16; i += NTHR) dst[i] = src[i];
    }
    __syncthreads();

    // ---------------- Tensor-core GEMM: D = Ah*Bh + Ah*Bl + Al*Bh -------------
    // warp tile m32 x n64; term-fused: A frags loaded once per kk, B frags once
    // per (kk, jp); each (kk, jp) issues all 12 MMAs.
    const int wm = (warp & 3) * 32;
    const int wn = (warp >> 2) * 64;

    float acc0[8][4], acc1[8][4];
    #pragma unroll
    for (int j = 0; j < 8; j++)
        #pragma unroll
        for (int q = 0; q < 4; q++) { acc0[j][q] = 0.f; acc1[j][q] = 0.f; }

    const uint32_t arow0 = ((uint32_t)(wm + (lane & 15)) * STRD + ((lane >> 4) << 3)) * 2;
    const uint32_t arow1 = arow0 + 16 * (STRD * 2);
    const uint32_t brow  = ((uint32_t)(wn + (lane & 7) + ((lane & 16) >> 1)) * STRD) * 2
                         + (lane & 8) * 2;

    #pragma unroll
    for (int kk = 0; kk < 5; kk++) {
        uint32_t ah0[4], ah1[4], al0[4], al1[4];
        ldsm_x4(ah0, smem_base + SM_AHI + arow0 + kk * 32);
        ldsm_x4(ah1, smem_base + SM_AHI + arow1 + kk * 32);
        ldsm_x4(al0, smem_base + SM_ALO + arow0 + kk * 32);
        ldsm_x4(al1, smem_base + SM_ALO + arow1 + kk * 32);
        #pragma unroll
        for (int jp = 0; jp < 4; jp++) {
            uint32_t bh[4], bl[4];
            ldsm_x4(bh, smem_base + SM_BHI + brow + (uint32_t)jp * 16 * (STRD * 2) + kk * 32);
            ldsm_x4(bl, smem_base + SM_BLO + brow + (uint32_t)jp * 16 * (STRD * 2) + kk * 32);
            mma_bf16(acc0[2*jp],     ah0, bh);
            mma_bf16(acc0[2*jp + 1], ah0, bh + 2);
            mma_bf16(acc1[2*jp],     ah1, bh);
            mma_bf16(acc1[2*jp + 1], ah1, bh + 2);
            mma_bf16(acc0[2*jp],     ah0, bl);
            mma_bf16(acc0[2*jp + 1], ah0, bl + 2);
            mma_bf16(acc1[2*jp],     ah1, bl);
            mma_bf16(acc1[2*jp + 1], ah1, bl + 2);
            mma_bf16(acc0[2*jp],     al0, bh);
            mma_bf16(acc0[2*jp + 1], al0, bh + 2);
            mma_bf16(acc1[2*jp],     al1, bh);
            mma_bf16(acc1[2*jp + 1], al1, bh + 2);
        }
    }

    // ---------------- Epilogue: bias + relu + STG.64 --------------------------
    {
        const float* bs = reinterpret_cast<const float*>(smem + SM_BSELF);
        const int rb  = wm + (lane >> 2);
        const int c00 = wn + 2 * (lane & 3);
        #pragma unroll
        for (int mi = 0; mi < 2; mi++) {
            const int rr = rb + 16 * mi;
            float* orow0 = out + (size_t)(row0 + rr) * CC;
            float* orow1 = out + (size_t)(row0 + rr + 8) * CC;
            #pragma unroll
            for (int j = 0; j < 8; j++) {
                const float (*av)[4] = mi ? acc1 : acc0;
                int c = c00 + 8 * j;
                float b0 = bs[c], b1 = bs[c + 1];
                float2 v0, v1;
                v0.x = fmaxf(av[j][0] + b0, 0.f);
                v0.y = fmaxf(av[j][1] + b1, 0.f);
                v1.x = fmaxf(av[j][2] + b0, 0.f);
                v1.y = fmaxf(av[j][3] + b1, 0.f);
                *reinterpret_cast<float2*>(orow0 + c) = v0;
                *reinterpret_cast<float2*>(orow1 + c) = v1;
            }
        }
    }
    __syncthreads();   // order epilogue STGs before rare-row RMW (same CTA/SM)

    // ---------------- Rare rows (deg<5, ~3.8%): warp-parallel zni patch -------
    const int nr = *reinterpret_cast<int*>(smem + SM_NRARE);
    float* sfp = reinterpret_cast<float*>(smem + SM_SFW) + warp * 72;
    const float* bsum = reinterpret_cast<const float*>(smem + SM_BSUM);
    for (int i = warp; i < nr; i += 8) {
        int packed = reinterpret_cast<int*>(smem + SM_RARE)[i];
        int r  = packed & 0xFF;
        int dg = packed >> 8;
        int e[DD];
        #pragma unroll
        for (int d = 0; d < DD; d++) e[d] = edges[(size_t)(row0 + r) * DD + d];
        #pragma unroll
        for (int f = lane; f < FAN; f += 32) {
            float s;
            if (f < FA) {
                s = 0.f;
                #pragma unroll
                for (int d = 0; d < DD; d++)
                    if (e[d] >= 0) s += atoms[((size_t)(bidx * MM + e[d])) * FA + f];
            } else {
                s = bsum[r * FB + (f - FA)];     // fp32 bond sums from smem
            }
            sfp[f] = s;
        }
        __syncwarp();
        const float4* bi4 = reinterpret_cast<const float4*>(b_inner) + dg * 32 + lane;
        const float4* w4  = reinterpret_cast<const float4*>(W_inner) + ((size_t)dg * FAN) * 32 + lane;
        float4 z = __ldg(bi4);
        #pragma unroll
        for (int f = 0; f < FAN; f++) {
            float  s = sfp[f];
            float4 w = __ldg(w4 + (size_t)f * 32);
            z.x = fmaf(s, w.x, z.x);
            z.y = fmaf(s, w.y, z.y);
            z.z = fmaf(s, w.z, z.z);
            z.w = fmaf(s, w.w, z.w);
        }
        float4* op = reinterpret_cast<float4*>(out + (size_t)(row0 + r) * CC) + lane;
        float4 cur = *op;
        cur.x += fmaxf(z.x, 0.f);
        cur.y += fmaxf(z.y, 0.f);
        cur.z += fmaxf(z.z, 0.f);
        cur.w += fmaxf(z.w, 0.f);
        *op = cur;
        __syncwarp();
    }
}

extern "C" void kernel_launch(void* const* d_in, const int* in_sizes, int n_in,
                              void* d_out, int out_size) {
    const float* atoms   = (const float*)d_in[0];
    const float* bonds   = (const float*)d_in[1];
    const int*   edges   = (const int*)  d_in[2];
    const float* W_inner = (const float*)d_in[3];
    const float* b_inner = (const float*)d_in[4];
    const float* W_self  = (const float*)d_in[5];
    const float* b_self  = (const float*)d_in[6];
    float* out = (float*)d_out;

    prep_kernel<<<KP, CC>>>(W_self);

    cudaFuncSetAttribute(tga_kernel, cudaFuncAttributeMaxDynamicSharedMemorySize, SM_TOTAL);

    // PDL launch: main kernel may begin staging while prep finishes.
    cudaLaunchConfig_t cfg = {};
    cfg.gridDim  = dim3(BB, 1, 1);
    cfg.blockDim = dim3(NTHR, 1, 1);
    cfg.dynamicSmemBytes = SM_TOTAL;
    cfg.stream = 0;
    cudaLaunchAttribute at[1];
    at[0].id = cudaLaunchAttributeProgrammaticStreamSerialization;
    at[0].val.programmaticStreamSerializationAllowed = 1;
    cfg.attrs = at;
    cfg.numAttrs = 1;
    cudaLaunchKernelEx(&cfg, tga_kernel, atoms, bonds, edges,
                       W_inner, b_inner, b_self, out);
}

// round 12
// speedup vs baseline: 2.8059x; 1.0231x over previous
#include <cuda_runtime.h>
#include <cuda_bf16.h>
#include <cstdint>

// Problem constants
#define BB   2048
#define MM   128
#define FA   62
#define FB   6
#define DD   5
#define CC   128
#define FAN  68
#define NTHR 256
#define KP   80            // K padded to 5 mma-steps of 16
#define STRD 88            // smem row stride in bf16 (176 B -> ldmatrix conflict-free)

// SMEM byte offsets
#define SM_AHI   0                       // 128 x 88 bf16 = 22528
#define SM_ALO   22528
#define SM_BHI   45056                   // B image dst (bulk copy), 45056 B
#define SM_BLO   67584
#define SM_BSELF 90112                   // float[128]
#define SM_SFW   90624                   // 8 warps * 72 floats
#define SM_RARE  92928                   // int[128]
#define SM_NRARE 93440
#define SM_BSUM  93444                   // float[128*6] fp32 bond sums (tail reuse)
#define SM_MBAR  96520                   // 2 x 8B mbarriers (bonds, btile)
#define SM_BRAW  96544                   // raw bonds staging, 15360 B
#define SM_TOTAL 111904

#define BTILE_BYTES 45056
#define BRAW_BYTES  (MM * DD * FB * 4)   // 15360
// Pre-split W_self image (bf16 hi | lo), exact smem layout, built once per launch.
__device__ __align__(16) unsigned char g_btile[BTILE_BYTES];

__device__ __forceinline__ uint32_t smem_to_u32(const void* p) {
    uint32_t a;
    asm("{ .reg .u64 t; cvta.to.shared.u64 t, %1; cvt.u32.u64 %0, t; }" : "=r"(a) : "l"(p));
    return a;
}
__device__ __forceinline__ void ldsm_x4(uint32_t* r, uint32_t addr) {
    asm volatile("ldmatrix.sync.aligned.m8n8.x4.shared.b16 {%0,%1,%2,%3}, [%4];"
                 : "=r"(r[0]), "=r"(r[1]), "=r"(r[2]), "=r"(r[3]) : "r"(addr));
}
__device__ __forceinline__ void mma_bf16(float* d, const uint32_t* a, const uint32_t* b) {
    asm volatile("mma.sync.aligned.m16n8k16.row.col.f32.bf16.bf16.f32 "
                 "{%0,%1,%2,%3}, {%4,%5,%6,%7}, {%8,%9}, {%0,%1,%2,%3};"
                 : "+f"(d[0]), "+f"(d[1]), "+f"(d[2]), "+f"(d[3])
                 : "r"(a[0]), "r"(a[1]), "r"(a[2]), "r"(a[3]), "r"(b[0]), "r"(b[1]));
}
// fp32 pair -> packed bf16x2 hi and lo (x = hi + lo to ~2^-18 relative)
__device__ __forceinline__ void split2(float x0, float x1, uint32_t& hi, uint32_t& lo) {
    __nv_bfloat162 h = __floats2bfloat162_rn(x0, x1);
    float h0 = __bfloat162float(__low2bfloat16(h));
    float h1 = __bfloat162float(__high2bfloat16(h));
    __nv_bfloat162 l = __floats2bfloat162_rn(x0 - h0, x1 - h1);
    hi = *reinterpret_cast<uint32_t*>(&h);
    lo = *reinterpret_cast<uint32_t*>(&l);
}
#define MBARRIER_INIT(mb, n) \
    asm volatile("mbarrier.init.shared.b64 [%0], %1;" :: "r"((uint32_t)(mb)), "r"((uint32_t)(n)) : "memory")
#define MBARRIER_EXPECT_TX(mb, bytes) \
    asm volatile("mbarrier.arrive.expect_tx.shared.b64 _, [%0], %1;" :: "r"((uint32_t)(mb)), "r"((uint32_t)(bytes)) : "memory")
#define MBARRIER_WAIT_PARITY(mb, ph) do { \
    uint32_t _mb = (uint32_t)(mb), _ph = (uint32_t)(ph), _done; \
    asm volatile("{ .reg .pred p; mbarrier.try_wait.parity.acquire.cta.shared::cta.b64 p, [%1], %2; selp.b32 %0, 1, 0, p; }" \
                 : "=r"(_done) : "r"(_mb), "r"(_ph) : "memory"); \
    if (!_done) { \
        asm volatile("{ .reg .pred P1; WL_%=: mbarrier.try_wait.parity.acquire.cta.shared::cta.b64 P1, [%0], %1, 0x989680; @P1 bra.uni WD_%=; bra.uni WL_%=; WD_%=: }" \
                     :: "r"(_mb), "r"(_ph) : "memory"); \
    } \
} while (0)
__device__ __forceinline__ void bulk_g2s(uint32_t dst, const void* src, uint32_t bytes, uint32_t mbar) {
    asm volatile("cp.async.bulk.shared::cta.global.mbarrier::complete_tx::bytes [%0], [%1], %2, [%3];"
                 :: "r"(dst), "l"(src), "r"(bytes), "r"(mbar) : "memory");
}

// ---------------- Prep: W_self -> bf16 hi/lo padded image ------------------
__global__ void prep_kernel(const float* __restrict__ W_self) {
    const int k = blockIdx.x;        // 0..KP-1
    const int n = threadIdx.x;       // 0..127
    __nv_bfloat16 h = __float2bfloat16(0.f), l = h;
    if (k < FAN) {
        float w = W_self[(size_t)k * CC + n];
        h = __float2bfloat16(w);
        l = __float2bfloat16(w - __bfloat162float(h));
    }
    const uint32_t off = (uint32_t)n * (STRD * 2) + (uint32_t)k * 2;
    *reinterpret_cast<__nv_bfloat16*>(g_btile + off)                      = h;  // BHI
    *reinterpret_cast<__nv_bfloat16*>(g_btile + (SM_BLO - SM_BHI) + off)  = l;  // BLO
    // PDL: allow the dependent main kernel to start its independent staging.
    asm volatile("griddepcontrol.launch_dependents;");
}

__global__ __launch_bounds__(NTHR, 2)
void tga_kernel(const float* __restrict__ atoms,
                const float* __restrict__ bonds,
                const int*   __restrict__ edges,
                const float* __restrict__ W_inner,
                const float* __restrict__ b_inner,
                const float* __restrict__ b_self,
                float* __restrict__ out) {
    extern __shared__ char smem[];
    const uint32_t smem_base = smem_to_u32(smem);
    const int tid  = threadIdx.x;
    const int lane = tid & 31;
    const int warp = tid >> 5;
    const int row0 = blockIdx.x * MM;      // one batch per CTA
    const int bidx = blockIdx.x;

    if (tid == 0) {
        *reinterpret_cast<int*>(smem + SM_NRARE) = 0;
        MBARRIER_INIT(smem_base + SM_MBAR, 1);       // bonds
        MBARRIER_INIT(smem_base + SM_MBAR + 8, 1);   // B image
    }
    __syncthreads();    // mbarrier init visible before async use

    // ---------------- Kick off bonds DMA (no dependency) --------------------
    if (tid == 0) {
        MBARRIER_EXPECT_TX(smem_base + SM_MBAR, BRAW_BYTES);
        bulk_g2s(smem_base + SM_BRAW, bonds + (size_t)row0 * DD * FB,
                 BRAW_BYTES, smem_base + SM_MBAR);
    }

    // ---------------- Atoms -> A tiles k 0..61, fully coalesced -------------
    {
        const float2* a2 = reinterpret_cast<const float2*>(atoms + (size_t)row0 * FA);
        #pragma unroll
        for (int idx = tid; idx < MM * 31; idx += NTHR) {
            int r = idx / 31, j = idx % 31;          // f = 2j, 2j+1
            float2 v = a2[idx];                       // lane-consecutive: coalesced
            uint32_t hi, lo;
            split2(v.x, v.y, hi, lo);
            *reinterpret_cast<uint32_t*>(smem + SM_AHI + r * (STRD*2) + 4*j) = hi;
            *reinterpret_cast<uint32_t*>(smem + SM_ALO + r * (STRD*2) + 4*j) = lo;
        }
    }

    // ---------------- Kick off B-image DMA (after prep, via PDL) ------------
    asm volatile("griddepcontrol.wait;" ::: "memory");
    if (tid == 0) {
        MBARRIER_EXPECT_TX(smem_base + SM_MBAR + 8, BTILE_BYTES);
        bulk_g2s(smem_base + SM_BHI, g_btile, BTILE_BYTES, smem_base + SM_MBAR + 8);
    }

    // bias, degree + rare list
    if (tid < CC) reinterpret_cast<float*>(smem + SM_BSELF)[tid] = b_self[tid];
    if (tid >= CC && tid < CC + MM) {
        const int r = tid - CC;
        const int* ep = edges + (size_t)(row0 + r) * DD;
        int dg = 0;
        #pragma unroll
        for (int d = 0; d < DD; d++) dg += (ep[d] >= 0);
        if (dg < DD) {
            int p = atomicAdd(reinterpret_cast<int*>(smem + SM_NRARE), 1);
            reinterpret_cast<int*>(smem + SM_RARE)[p] = r | (dg << 8);
        }
    }

    // ---------------- Bond sums (after bonds DMA lands) ----------------------
    MBARRIER_WAIT_PARITY(smem_base + SM_MBAR, 0);
    if (tid < MM) {
        const float* bb = reinterpret_cast<const float*>(smem + SM_BRAW) + tid * (DD * FB);
        float bs[FB];
        #pragma unroll
        for (int f = 0; f < FB; f++) bs[f] = 0.f;
        #pragma unroll
        for (int d = 0; d < DD; d++)
            #pragma unroll
            for (int f = 0; f < FB; f++) bs[f] += bb[d * FB + f];
        // fp32 sums for the rare tail
        float* bsum = reinterpret_cast<float*>(smem + SM_BSUM) + tid * FB;
        #pragma unroll
        for (int f = 0; f < FB; f++) bsum[f] = bs[f];
        // bf16 hi/lo -> A tiles k 62..67, zeros k 68..79
        char* ah = smem + SM_AHI + tid * (STRD*2);
        char* al = smem + SM_ALO + tid * (STRD*2);
        #pragma unroll
        for (int p = 0; p < 3; p++) {
            uint32_t hi, lo;
            split2(bs[2*p], bs[2*p + 1], hi, lo);
            *reinterpret_cast<uint32_t*>(ah + 4*(31 + p)) = hi;
            *reinterpret_cast<uint32_t*>(al + 4*(31 + p)) = lo;
        }
        #pragma unroll
        for (int j = 34; j < 40; j++) {
            *reinterpret_cast<uint32_t*>(ah + 4*j) = 0u;
            *reinterpret_cast<uint32_t*>(al + 4*j) = 0u;
        }
    }
    __syncthreads();                                  // A tiles complete
    MBARRIER_WAIT_PARITY(smem_base + SM_MBAR + 8, 0); // B image complete

    // ---------------- Tensor-core GEMM: D = Ah*Bh + Ah*Bl + Al*Bh -------------
    // warp tile m32 x n64; term-fused: A frags loaded once per kk, B frags once
    // per (kk, jp); each (kk, jp) issues all 12 MMAs.
    const int wm = (warp & 3) * 32;
    const int wn = (warp >> 2) * 64;

    float acc0[8][4], acc1[8][4];
    #pragma unroll
    for (int j = 0; j < 8; j++)
        #pragma unroll
        for (int q = 0; q < 4; q++) { acc0[j][q] = 0.f; acc1[j][q] = 0.f; }

    const uint32_t arow0 = ((uint32_t)(wm + (lane & 15)) * STRD + ((lane >> 4) << 3)) * 2;
    const uint32_t arow1 = arow0 + 16 * (STRD * 2);
    const uint32_t brow  = ((uint32_t)(wn + (lane & 7) + ((lane & 16) >> 1)) * STRD) * 2
                         + (lane & 8) * 2;

    #pragma unroll
    for (int kk = 0; kk < 5; kk++) {
        uint32_t ah0[4], ah1[4], al0[4], al1[4];
        ldsm_x4(ah0, smem_base + SM_AHI + arow0 + kk * 32);
        ldsm_x4(ah1, smem_base + SM_AHI + arow1 + kk * 32);
        ldsm_x4(al0, smem_base + SM_ALO + arow0 + kk * 32);
        ldsm_x4(al1, smem_base + SM_ALO + arow1 + kk * 32);
        #pragma unroll
        for (int jp = 0; jp < 4; jp++) {
            uint32_t bh[4], bl[4];
            ldsm_x4(bh, smem_base + SM_BHI + brow + (uint32_t)jp * 16 * (STRD * 2) + kk * 32);
            ldsm_x4(bl, smem_base + SM_BLO + brow + (uint32_t)jp * 16 * (STRD * 2) + kk * 32);
            mma_bf16(acc0[2*jp],     ah0, bh);
            mma_bf16(acc0[2*jp + 1], ah0, bh + 2);
            mma_bf16(acc1[2*jp],     ah1, bh);
            mma_bf16(acc1[2*jp + 1], ah1, bh + 2);
            mma_bf16(acc0[2*jp],     ah0, bl);
            mma_bf16(acc0[2*jp + 1], ah0, bl + 2);
            mma_bf16(acc1[2*jp],     ah1, bl);
            mma_bf16(acc1[2*jp + 1], ah1, bl + 2);
            mma_bf16(acc0[2*jp],     al0, bh);
            mma_bf16(acc0[2*jp + 1], al0, bh + 2);
            mma_bf16(acc1[2*jp],     al1, bh);
            mma_bf16(acc1[2*jp + 1], al1, bh + 2);
        }
    }

    // ---------------- Epilogue: bias + relu + STG.64 --------------------------
    {
        const float* bs = reinterpret_cast<const float*>(smem + SM_BSELF);
        const int rb  = wm + (lane >> 2);
        const int c00 = wn + 2 * (lane & 3);
        #pragma unroll
        for (int mi = 0; mi < 2; mi++) {
            const int rr = rb + 16 * mi;
            float* orow0 = out + (size_t)(row0 + rr) * CC;
            float* orow1 = out + (size_t)(row0 + rr + 8) * CC;
            #pragma unroll
            for (int j = 0; j < 8; j++) {
                const float (*av)[4] = mi ? acc1 : acc0;
                int c = c00 + 8 * j;
                float b0 = bs[c], b1 = bs[c + 1];
                float2 v0, v1;
                v0.x = fmaxf(av[j][0] + b0, 0.f);
                v0.y = fmaxf(av[j][1] + b1, 0.f);
                v1.x = fmaxf(av[j][2] + b0, 0.f);
                v1.y = fmaxf(av[j][3] + b1, 0.f);
                *reinterpret_cast<float2*>(orow0 + c) = v0;
                *reinterpret_cast<float2*>(orow1 + c) = v1;
            }
        }
    }
    __syncthreads();   // order epilogue STGs before rare-row RMW (same CTA/SM)

    // ---------------- Rare rows (deg<5, ~3.8%): warp-parallel zni patch -------
    const int nr = *reinterpret_cast<int*>(smem + SM_NRARE);
    float* sfp = reinterpret_cast<float*>(smem + SM_SFW) + warp * 72;
    const float* bsum = reinterpret_cast<const float*>(smem + SM_BSUM);
    for (int i = warp; i < nr; i += 8) {
        int packed = reinterpret_cast<int*>(smem + SM_RARE)[i];
        int r  = packed & 0xFF;
        int dg = packed >> 8;
        int e[DD];
        #pragma unroll
        for (int d = 0; d < DD; d++) e[d] = edges[(size_t)(row0 + r) * DD + d];
        #pragma unroll
        for (int f = lane; f < FAN; f += 32) {
            float s;
            if (f < FA) {
                s = 0.f;
                #pragma unroll
                for (int d = 0; d < DD; d++)
                    if (e[d] >= 0) s += atoms[((size_t)(bidx * MM + e[d])) * FA + f];
            } else {
                s = bsum[r * FB + (f - FA)];     // fp32 bond sums from smem
            }
            sfp[f] = s;
        }
        __syncwarp();
        const float4* bi4 = reinterpret_cast<const float4*>(b_inner) + dg * 32 + lane;
        const float4* w4  = reinterpret_cast<const float4*>(W_inner) + ((size_t)dg * FAN) * 32 + lane;
        float4 z = __ldg(bi4);
        #pragma unroll
        for (int f = 0; f < FAN; f++) {
            float  s = sfp[f];
            float4 w = __ldg(w4 + (size_t)f * 32);
            z.x = fmaf(s, w.x, z.x);
            z.y = fmaf(s, w.y, z.y);
            z.z = fmaf(s, w.z, z.z);
            z.w = fmaf(s, w.w, z.w);
        }
        float4* op = reinterpret_cast<float4*>(out + (size_t)(row0 + r) * CC) + lane;
        float4 cur = *op;
        cur.x += fmaxf(z.x, 0.f);
        cur.y += fmaxf(z.y, 0.f);
        cur.z += fmaxf(z.z, 0.f);
        cur.w += fmaxf(z.w, 0.f);
        *op = cur;
        __syncwarp();
    }
}

extern "C" void kernel_launch(void* const* d_in, const int* in_sizes, int n_in,
                              void* d_out, int out_size) {
    const float* atoms   = (const float*)d_in[0];
    const float* bonds   = (const float*)d_in[1];
    const int*   edges   = (const int*)  d_in[2];
    const float* W_inner = (const float*)d_in[3];
    const float* b_inner = (const float*)d_in[4];
    const float* W_self  = (const float*)d_in[5];
    const float* b_self  = (const float*)d_in[6];
    float* out = (float*)d_out;

    prep_kernel<<<KP, CC>>>(W_self);

    cudaFuncSetAttribute(tga_kernel, cudaFuncAttributeMaxDynamicSharedMemorySize, SM_TOTAL);

    // PDL launch: main kernel may begin staging while prep finishes.
    cudaLaunchConfig_t cfg = {};
    cfg.gridDim  = dim3(BB, 1, 1);
    cfg.blockDim = dim3(NTHR, 1, 1);
    cfg.dynamicSmemBytes = SM_TOTAL;
    cfg.stream = 0;
    cudaLaunchAttribute at[1];
    at[0].id = cudaLaunchAttributeProgrammaticStreamSerialization;
    at[0].val.programmaticStreamSerializationAllowed = 1;
    cfg.attrs = at;
    cfg.numAttrs = 1;
    cudaLaunchKernelEx(&cfg, tga_kernel, atoms, bonds, edges,
                       W_inner, b_inner, b_self, out);
}

// round 14
// speedup vs baseline: 2.8852x; 1.0282x over previous
#include <cuda_runtime.h>
#include <cuda_bf16.h>
#include <cstdint>

// Problem constants
#define BB   2048
#define MM   128
#define FA   62
#define FB   6
#define DD   5
#define CC   128
#define FAN  68
#define NTHR 256
#define KP   80            // K padded to 5 mma-steps of 16
#define STRD 88            // smem row stride in bf16 (176 B -> ldmatrix conflict-free)

// SMEM byte offsets
#define SM_AHI   0                       // 128 x 88 bf16 = 22528
#define SM_ALO   22528
#define SM_BHI   45056                   // B image dst (bulk copy), 45056 B
#define SM_BLO   67584
#define SM_BSELF 90112                   // float[128]
#define SM_SFW   90624                   // 8 warps * 72 floats
#define SM_RARE  92928                   // int[128]
#define SM_NRARE 93440
#define SM_BSUM  93444                   // float[128*6] fp32 bond sums (tail reuse)
#define SM_MBAR  96520                   // 2 x 8B mbarriers (bonds, btile)
#define SM_BRAW  96544                   // raw bonds staging, 15360 B
#define SM_TOTAL 111904

#define BTILE_BYTES 45056
#define BRAW_BYTES  (MM * DD * FB * 4)   // 15360
// Pre-split W_self image (bf16 hi | lo), exact smem layout, built once per launch.
__device__ __align__(16) unsigned char g_btile[BTILE_BYTES];

__device__ __forceinline__ uint32_t smem_to_u32(const void* p) {
    uint32_t a;
    asm("{ .reg .u64 t; cvta.to.shared.u64 t, %1; cvt.u32.u64 %0, t; }" : "=r"(a) : "l"(p));
    return a;
}
__device__ __forceinline__ void ldsm_x4(uint32_t* r, uint32_t addr) {
    asm volatile("ldmatrix.sync.aligned.m8n8.x4.shared.b16 {%0,%1,%2,%3}, [%4];"
                 : "=r"(r[0]), "=r"(r[1]), "=r"(r[2]), "=r"(r[3]) : "r"(addr));
}
__device__ __forceinline__ void mma_bf16(float* d, const uint32_t* a, const uint32_t* b) {
    asm volatile("mma.sync.aligned.m16n8k16.row.col.f32.bf16.bf16.f32 "
                 "{%0,%1,%2,%3}, {%4,%5,%6,%7}, {%8,%9}, {%0,%1,%2,%3};"
                 : "+f"(d[0]), "+f"(d[1]), "+f"(d[2]), "+f"(d[3])
                 : "r"(a[0]), "r"(a[1]), "r"(a[2]), "r"(a[3]), "r"(b[0]), "r"(b[1]));
}
// fp32 pair -> packed bf16x2 hi and lo (x = hi + lo to ~2^-18 relative)
__device__ __forceinline__ void split2(float x0, float x1, uint32_t& hi, uint32_t& lo) {
    __nv_bfloat162 h = __floats2bfloat162_rn(x0, x1);
    float h0 = __bfloat162float(__low2bfloat16(h));
    float h1 = __bfloat162float(__high2bfloat16(h));
    __nv_bfloat162 l = __floats2bfloat162_rn(x0 - h0, x1 - h1);
    hi = *reinterpret_cast<uint32_t*>(&h);
    lo = *reinterpret_cast<uint32_t*>(&l);
}
#define MBARRIER_INIT(mb, n) \
    asm volatile("mbarrier.init.shared.b64 [%0], %1;" :: "r"((uint32_t)(mb)), "r"((uint32_t)(n)) : "memory")
#define MBARRIER_EXPECT_TX(mb, bytes) \
    asm volatile("mbarrier.arrive.expect_tx.shared.b64 _, [%0], %1;" :: "r"((uint32_t)(mb)), "r"((uint32_t)(bytes)) : "memory")
#define MBARRIER_WAIT_PARITY(mb, ph) do { \
    uint32_t _mb = (uint32_t)(mb), _ph = (uint32_t)(ph), _done; \
    asm volatile("{ .reg .pred p; mbarrier.try_wait.parity.acquire.cta.shared::cta.b64 p, [%1], %2; selp.b32 %0, 1, 0, p; }" \
                 : "=r"(_done) : "r"(_mb), "r"(_ph) : "memory"); \
    if (!_done) { \
        asm volatile("{ .reg .pred P1; WL_%=: mbarrier.try_wait.parity.acquire.cta.shared::cta.b64 P1, [%0], %1, 0x989680; @P1 bra.uni WD_%=; bra.uni WL_%=; WD_%=: }" \
                     :: "r"(_mb), "r"(_ph) : "memory"); \
    } \
} while (0)
#define BAR_SYNC(id, cnt) \
    asm volatile("bar.sync %0, %1;" :: "r"(id), "r"(cnt) : "memory")
__device__ __forceinline__ void bulk_g2s(uint32_t dst, const void* src, uint32_t bytes, uint32_t mbar) {
    asm volatile("cp.async.bulk.shared::cta.global.mbarrier::complete_tx::bytes [%0], [%1], %2, [%3];"
                 :: "r"(dst), "l"(src), "r"(bytes), "r"(mbar) : "memory");
}

// ---------------- Prep: W_self -> bf16 hi/lo padded image ------------------
__global__ void prep_kernel(const float* __restrict__ W_self) {
    const int k = blockIdx.x;        // 0..KP-1
    const int n = threadIdx.x;       // 0..127
    __nv_bfloat16 h = __float2bfloat16(0.f), l = h;
    if (k < FAN) {
        float w = W_self[(size_t)k * CC + n];
        h = __float2bfloat16(w);
        l = __float2bfloat16(w - __bfloat162float(h));
    }
    const uint32_t off = (uint32_t)n * (STRD * 2) + (uint32_t)k * 2;
    *reinterpret_cast<__nv_bfloat16*>(g_btile + off)                      = h;  // BHI
    *reinterpret_cast<__nv_bfloat16*>(g_btile + (SM_BLO - SM_BHI) + off)  = l;  // BLO
    asm volatile("griddepcontrol.launch_dependents;");
}

__global__ __launch_bounds__(NTHR, 2)
void tga_kernel(const float* __restrict__ atoms,
                const float* __restrict__ bonds,
                const int*   __restrict__ edges,
                const float* __restrict__ W_inner,
                const float* __restrict__ b_inner,
                const float* __restrict__ b_self,
                float* __restrict__ out) {
    extern __shared__ char smem[];
    const uint32_t smem_base = smem_to_u32(smem);
    const int tid  = threadIdx.x;
    const int lane = tid & 31;
    const int warp = tid >> 5;
    const int row0 = blockIdx.x * MM;      // one batch per CTA
    const int bidx = blockIdx.x;

    // per-warp tile coordinates (GEMM: m32 x n64; pair {w, w+4} shares m rows)
    const int pm   = warp & 3;             // m-pair id 0..3
    const int half = warp >> 2;            // 0 | 1
    const int rbase = pm * 32 + half * 16; // 16 A-rows owned by this warp
    const int wm = pm * 32;
    const int wn = half * 64;

    if (tid == 0) {
        *reinterpret_cast<int*>(smem + SM_NRARE) = 0;
        MBARRIER_INIT(smem_base + SM_MBAR, 1);       // bonds
        MBARRIER_INIT(smem_base + SM_MBAR + 8, 1);   // B image
    }
    __syncthreads();    // mbarrier init + nrare visible

    // ---------------- DMAs (warp 0 lane 0 issues; others stream ahead) ------
    if (tid == 0) {
        MBARRIER_EXPECT_TX(smem_base + SM_MBAR, BRAW_BYTES);
        bulk_g2s(smem_base + SM_BRAW, bonds + (size_t)row0 * DD * FB,
                 BRAW_BYTES, smem_base + SM_MBAR);
        asm volatile("griddepcontrol.wait;" ::: "memory");   // prep's g_btile ready
        MBARRIER_EXPECT_TX(smem_base + SM_MBAR + 8, BTILE_BYTES);
        bulk_g2s(smem_base + SM_BHI, g_btile, BTILE_BYTES, smem_base + SM_MBAR + 8);
    }
    if (tid < CC) reinterpret_cast<float*>(smem + SM_BSELF)[tid] = b_self[tid];

    // ---------------- Per-warp: stage own 16 atom rows (coalesced) ----------
    {
        const float2* a2 = reinterpret_cast<const float2*>(atoms);
        const size_t gbase = (size_t)(row0 + rbase) * 31;   // rows contiguous: r*31+j flat
        #pragma unroll
        for (int i = 0; i < 16; i++) {
            int idx = i * 32 + lane;                        // 0..495 (+16 masked)
            if (idx < 16 * 31) {
                float2 v = a2[gbase + idx];
                int r = idx / 31, j = idx - r * 31;
                uint32_t hi, lo;
                split2(v.x, v.y, hi, lo);
                *reinterpret_cast<uint32_t*>(smem + SM_AHI + (rbase + r) * (STRD*2) + 4*j) = hi;
                *reinterpret_cast<uint32_t*>(smem + SM_ALO + (rbase + r) * (STRD*2) + 4*j) = lo;
            }
        }
    }

    // ---------------- Per-warp: degree + rare list for own rows -------------
    if (lane < 16) {
        const int r = rbase + lane;
        const int* ep = edges + (size_t)(row0 + r) * DD;
        int dg = 0;
        #pragma unroll
        for (int d = 0; d < DD; d++) dg += (ep[d] >= 0);
        if (dg < DD) {
            int p = atomicAdd(reinterpret_cast<int*>(smem + SM_NRARE), 1);
            reinterpret_cast<int*>(smem + SM_RARE)[p] = r | (dg << 8);
        }
    }

    // ---------------- Per-warp: bond sums for own rows (after bonds DMA) ----
    MBARRIER_WAIT_PARITY(smem_base + SM_MBAR, 0);
    if (lane < 16) {
        const int r = rbase + lane;
        const float* bb = reinterpret_cast<const float*>(smem + SM_BRAW) + r * (DD * FB);
        float bs[FB];
        #pragma unroll
        for (int f = 0; f < FB; f++) bs[f] = 0.f;
        #pragma unroll
        for (int d = 0; d < DD; d++)
            #pragma unroll
            for (int f = 0; f < FB; f++) bs[f] += bb[d * FB + f];
        float* bsum = reinterpret_cast<float*>(smem + SM_BSUM) + r * FB;
        #pragma unroll
        for (int f = 0; f < FB; f++) bsum[f] = bs[f];
        char* ah = smem + SM_AHI + r * (STRD*2);
        char* al = smem + SM_ALO + r * (STRD*2);
        #pragma unroll
        for (int p = 0; p < 3; p++) {
            uint32_t hi, lo;
            split2(bs[2*p], bs[2*p + 1], hi, lo);
            *reinterpret_cast<uint32_t*>(ah + 4*(31 + p)) = hi;
            *reinterpret_cast<uint32_t*>(al + 4*(31 + p)) = lo;
        }
        #pragma unroll
        for (int j = 34; j < 40; j++) {                    // k pad 68..79
            *reinterpret_cast<uint32_t*>(ah + 4*j) = 0u;
            *reinterpret_cast<uint32_t*>(al + 4*j) = 0u;
        }
    }

    // Pair barrier: rows wm..wm+31 fully staged by warps {pm, pm+4}.
    BAR_SYNC(pm + 1, 64);
    // B image complete (per-warp wait; first waiter blocks, rest fall through)
    MBARRIER_WAIT_PARITY(smem_base + SM_MBAR + 8, 0);

    // ---------------- Tensor-core GEMM: D = Ah*Bh + Ah*Bl + Al*Bh -------------
    float acc0[8][4], acc1[8][4];
    #pragma unroll
    for (int j = 0; j < 8; j++)
        #pragma unroll
        for (int q = 0; q < 4; q++) { acc0[j][q] = 0.f; acc1[j][q] = 0.f; }

    const uint32_t arow0 = ((uint32_t)(wm + (lane & 15)) * STRD + ((lane >> 4) << 3)) * 2;
    const uint32_t arow1 = arow0 + 16 * (STRD * 2);
    const uint32_t brow  = ((uint32_t)(wn + (lane & 7) + ((lane & 16) >> 1)) * STRD) * 2
                         + (lane & 8) * 2;

    #pragma unroll
    for (int kk = 0; kk < 5; kk++) {
        uint32_t ah0[4], ah1[4], al0[4], al1[4];
        ldsm_x4(ah0, smem_base + SM_AHI + arow0 + kk * 32);
        ldsm_x4(ah1, smem_base + SM_AHI + arow1 + kk * 32);
        ldsm_x4(al0, smem_base + SM_ALO + arow0 + kk * 32);
        ldsm_x4(al1, smem_base + SM_ALO + arow1 + kk * 32);
        #pragma unroll
        for (int jp = 0; jp < 4; jp++) {
            uint32_t bh[4], bl[4];
            ldsm_x4(bh, smem_base + SM_BHI + brow + (uint32_t)jp * 16 * (STRD * 2) + kk * 32);
            ldsm_x4(bl, smem_base + SM_BLO + brow + (uint32_t)jp * 16 * (STRD * 2) + kk * 32);
            mma_bf16(acc0[2*jp],     ah0, bh);
            mma_bf16(acc0[2*jp + 1], ah0, bh + 2);
            mma_bf16(acc1[2*jp],     ah1, bh);
            mma_bf16(acc1[2*jp + 1], ah1, bh + 2);
            mma_bf16(acc0[2*jp],     ah0, bl);
            mma_bf16(acc0[2*jp + 1], ah0, bl + 2);
            mma_bf16(acc1[2*jp],     ah1, bl);
            mma_bf16(acc1[2*jp + 1], ah1, bl + 2);
            mma_bf16(acc0[2*jp],     al0, bh);
            mma_bf16(acc0[2*jp + 1], al0, bh + 2);
            mma_bf16(acc1[2*jp],     al1, bh);
            mma_bf16(acc1[2*jp + 1], al1, bh + 2);
        }
    }

    // ---------------- Epilogue: bias + relu + STG.64 --------------------------
    {
        const float* bs = reinterpret_cast<const float*>(smem + SM_BSELF);
        const int rb  = wm + (lane >> 2);
        const int c00 = wn + 2 * (lane & 3);
        #pragma unroll
        for (int mi = 0; mi < 2; mi++) {
            const int rr = rb + 16 * mi;
            float* orow0 = out + (size_t)(row0 + rr) * CC;
            float* orow1 = out + (size_t)(row0 + rr + 8) * CC;
            #pragma unroll
            for (int j = 0; j < 8; j++) {
                const float (*av)[4] = mi ? acc1 : acc0;
                int c = c00 + 8 * j;
                float b0 = bs[c], b1 = bs[c + 1];
                float2 v0, v1;
                v0.x = fmaxf(av[j][0] + b0, 0.f);
                v0.y = fmaxf(av[j][1] + b1, 0.f);
                v1.x = fmaxf(av[j][2] + b0, 0.f);
                v1.y = fmaxf(av[j][3] + b1, 0.f);
                *reinterpret_cast<float2*>(orow0 + c) = v0;
                *reinterpret_cast<float2*>(orow1 + c) = v1;
            }
        }
    }
    __syncthreads();   // all epilogue STGs + bsum before rare-row RMW

    // ---------------- Rare rows (deg<5, ~3.8%): warp-parallel zni patch -------
    const int nr = *reinterpret_cast<int*>(smem + SM_NRARE);
    float* sfp = reinterpret_cast<float*>(smem + SM_SFW) + warp * 72;
    const float* bsum = reinterpret_cast<const float*>(smem + SM_BSUM);
    for (int i = warp; i < nr; i += 8) {
        int packed = reinterpret_cast<int*>(smem + SM_RARE)[i];
        int r  = packed & 0xFF;
        int dg = packed >> 8;
        int e[DD];
        #pragma unroll
        for (int d = 0; d < DD; d++) e[d] = edges[(size_t)(row0 + r) * DD + d];
        #pragma unroll
        for (int f = lane; f < FAN; f += 32) {
            float s;
            if (f < FA) {
                s = 0.f;
                #pragma unroll
                for (int d = 0; d < DD; d++)
                    if (e[d] >= 0) s += atoms[((size_t)(bidx * MM + e[d])) * FA + f];
            } else {
                s = bsum[r * FB + (f - FA)];     // fp32 bond sums from smem
            }
            sfp[f] = s;
        }
        __syncwarp();
        const float4* bi4 = reinterpret_cast<const float4*>(b_inner) + dg * 32 + lane;
        const float4* w4  = reinterpret_cast<const float4*>(W_inner) + ((size_t)dg * FAN) * 32 + lane;
        float4 z = __ldg(bi4);
        #pragma unroll
        for (int f = 0; f < FAN; f++) {
            float  s = sfp[f];
            float4 w = __ldg(w4 + (size_t)f * 32);
            z.x = fmaf(s, w.x, z.x);
            z.y = fmaf(s, w.y, z.y);
            z.z = fmaf(s, w.z, z.z);
            z.w = fmaf(s, w.w, z.w);
        }
        float4* op = reinterpret_cast<float4*>(out + (size_t)(row0 + r) * CC) + lane;
        float4 cur = *op;
        cur.x += fmaxf(z.x, 0.f);
        cur.y += fmaxf(z.y, 0.f);
        cur.z += fmaxf(z.z, 0.f);
        cur.w += fmaxf(z.w, 0.f);
        *op = cur;
        __syncwarp();
    }
}

extern "C" void kernel_launch(void* const* d_in, const int* in_sizes, int n_in,
                              void* d_out, int out_size) {
    const float* atoms   = (const float*)d_in[0];
    const float* bonds   = (const float*)d_in[1];
    const int*   edges   = (const int*)  d_in[2];
    const float* W_inner = (const float*)d_in[3];
    const float* b_inner = (const float*)d_in[4];
    const float* W_self  = (const float*)d_in[5];
    const float* b_self  = (const float*)d_in[6];
    float* out = (float*)d_out;

    prep_kernel<<<KP, CC>>>(W_self);

    cudaFuncSetAttribute(tga_kernel, cudaFuncAttributeMaxDynamicSharedMemorySize, SM_TOTAL);

    // PDL launch: main kernel may begin staging while prep finishes.
    cudaLaunchConfig_t cfg = {};
    cfg.gridDim  = dim3(BB, 1, 1);
    cfg.blockDim = dim3(NTHR, 1, 1);
    cfg.dynamicSmemBytes = SM_TOTAL;
    cfg.stream = 0;
    cudaLaunchAttribute at[1];
    at[0].id = cudaLaunchAttributeProgrammaticStreamSerialization;
    at[0].val.programmaticStreamSerializationAllowed = 1;
    cfg.attrs = at;
    cfg.numAttrs = 1;
    cudaLaunchKernelEx(&cfg, tga_kernel, atoms, bonds, edges,
                       W_inner, b_inner, b_self, out);
}

// round 16
// speedup vs baseline: 3.0920x; 1.0717x over previous
#include <cuda_runtime.h>
#include <cstdint>

// Problem constants
#define BB   2048
#define MM   128
#define FA   62
#define FB   6
#define DD   5
#define CC   128
#define FAN  68
#define NTHR 256
#define KP   72            // K padded to 9 mma-steps of 8
#define NKK  9
#define STRDW 76           // smem row stride in words (76%32=12 -> frag reads conflict-free)
#define STRDB (STRDW * 4)

// SMEM byte offsets
#define SM_A     0                       // 128 x 76 f32(tf32) = 38912
#define SM_B     38912                   // 128n x 76k f32(tf32) = 38912 (DMA dst)
#define SM_BSELF 77824                   // float[128]
#define SM_SFW   78336                   // 8 warps * 72 floats
#define SM_RARE  80640                   // int[128]
#define SM_NRARE 81152
#define SM_BSUM  81168                   // float[128*6] fp32 bond sums (tail reuse)
#define SM_MBAR  84240                   // 2 x 8B mbarriers (bonds, btile)
#define SM_BRAW  84256                   // raw bonds staging, 15360 B
#define SM_TOTAL 99616

#define BTILE_BYTES 38912
#define BRAW_BYTES  (MM * DD * FB * 4)   // 15360
// Pre-converted W_self^T tf32 image, exact smem layout, built once per launch.
__device__ __align__(16) unsigned char g_btile[BTILE_BYTES];

__device__ __forceinline__ uint32_t smem_to_u32(const void* p) {
    uint32_t a;
    asm("{ .reg .u64 t; cvta.to.shared.u64 t, %1; cvt.u32.u64 %0, t; }" : "=r"(a) : "l"(p));
    return a;
}
__device__ __forceinline__ uint32_t f2tf(float f) {   // round-to-nearest tf32
    uint32_t r;
    asm("cvt.rna.tf32.f32 %0, %1;" : "=r"(r) : "f"(f));
    return r;
}
__device__ __forceinline__ uint32_t lds32(uint32_t addr) {  // shared-space load
    uint32_t v;
    asm volatile("ld.shared.b32 %0, [%1];" : "=r"(v) : "r"(addr));
    return v;
}
__device__ __forceinline__ void mma_tf32(float* d, const uint32_t* a, uint32_t b0, uint32_t b1) {
    asm volatile("mma.sync.aligned.m16n8k8.row.col.f32.tf32.tf32.f32 "
                 "{%0,%1,%2,%3}, {%4,%5,%6,%7}, {%8,%9}, {%0,%1,%2,%3};"
                 : "+f"(d[0]), "+f"(d[1]), "+f"(d[2]), "+f"(d[3])
                 : "r"(a[0]), "r"(a[1]), "r"(a[2]), "r"(a[3]), "r"(b0), "r"(b1));
}
#define MBARRIER_INIT(mb, n) \
    asm volatile("mbarrier.init.shared.b64 [%0], %1;" :: "r"((uint32_t)(mb)), "r"((uint32_t)(n)) : "memory")
#define MBARRIER_EXPECT_TX(mb, bytes) \
    asm volatile("mbarrier.arrive.expect_tx.shared.b64 _, [%0], %1;" :: "r"((uint32_t)(mb)), "r"((uint32_t)(bytes)) : "memory")
#define MBARRIER_WAIT_PARITY(mb, ph) do { \
    uint32_t _mb = (uint32_t)(mb), _ph = (uint32_t)(ph), _done; \
    asm volatile("{ .reg .pred p; mbarrier.try_wait.parity.acquire.cta.shared::cta.b64 p, [%1], %2; selp.b32 %0, 1, 0, p; }" \
                 : "=r"(_done) : "r"(_mb), "r"(_ph) : "memory"); \
    if (!_done) { \
        asm volatile("{ .reg .pred P1; WL_%=: mbarrier.try_wait.parity.acquire.cta.shared::cta.b64 P1, [%0], %1, 0x989680; @P1 bra.uni WD_%=; bra.uni WL_%=; WD_%=: }" \
                     :: "r"(_mb), "r"(_ph) : "memory"); \
    } \
} while (0)
#define BAR_SYNC(id, cnt) \
    asm volatile("bar.sync %0, %1;" :: "r"(id), "r"(cnt) : "memory")
__device__ __forceinline__ void bulk_g2s(uint32_t dst, const void* src, uint32_t bytes, uint32_t mbar) {
    asm volatile("cp.async.bulk.shared::cta.global.mbarrier::complete_tx::bytes [%0], [%1], %2, [%3];"
                 :: "r"(dst), "l"(src), "r"(bytes), "r"(mbar) : "memory");
}

// ---------------- Prep: W_self^T -> tf32-rounded f32 image ------------------
__global__ void prep_kernel(const float* __restrict__ W_self) {
    const int k = blockIdx.x;        // 0..KP-1
    const int n = threadIdx.x;       // 0..127
    uint32_t v = 0u;
    if (k < FAN) v = f2tf(W_self[(size_t)k * CC + n]);
    *reinterpret_cast<uint32_t*>(g_btile + ((uint32_t)n * STRDW + k) * 4) = v;
    asm volatile("griddepcontrol.launch_dependents;");
}

__global__ __launch_bounds__(NTHR, 2)
void tga_kernel(const float* __restrict__ atoms,
                const float* __restrict__ bonds,
                const int*   __restrict__ edges,
                const float* __restrict__ W_inner,
                const float* __restrict__ b_inner,
                const float* __restrict__ b_self,
                float* __restrict__ out) {
    extern __shared__ char smem[];
    const uint32_t smem_base = smem_to_u32(smem);
    const int tid  = threadIdx.x;
    const int lane = tid & 31;
    const int warp = tid >> 5;
    const int row0 = blockIdx.x * MM;      // one batch per CTA
    const int bidx = blockIdx.x;

    // per-warp tile coordinates (GEMM: m32 x n64; pair {w, w+4} shares m rows)
    const int pm   = warp & 3;
    const int half = warp >> 2;
    const int rbase = pm * 32 + half * 16; // 16 A-rows owned by this warp
    const int wm = pm * 32;
    const int wn = half * 64;

    if (tid == 0) {
        *reinterpret_cast<int*>(smem + SM_NRARE) = 0;
        MBARRIER_INIT(smem_base + SM_MBAR, 1);       // bonds
        MBARRIER_INIT(smem_base + SM_MBAR + 8, 1);   // B image
    }
    __syncthreads();

    // ---------------- DMAs -----------------------------------------------
    if (tid == 0) {
        MBARRIER_EXPECT_TX(smem_base + SM_MBAR, BRAW_BYTES);
        bulk_g2s(smem_base + SM_BRAW, bonds + (size_t)row0 * DD * FB,
                 BRAW_BYTES, smem_base + SM_MBAR);
        asm volatile("griddepcontrol.wait;" ::: "memory");   // prep's g_btile ready
        MBARRIER_EXPECT_TX(smem_base + SM_MBAR + 8, BTILE_BYTES);
        bulk_g2s(smem_base + SM_B, g_btile, BTILE_BYTES, smem_base + SM_MBAR + 8);
    }
    if (tid < CC) reinterpret_cast<float*>(smem + SM_BSELF)[tid] = b_self[tid];

    // ---------------- Per-warp: stage own 16 atom rows as tf32 -------------
    {
        const float2* a2 = reinterpret_cast<const float2*>(atoms);
        const size_t gbase = (size_t)(row0 + rbase) * 31;   // rows contiguous, flat
        #pragma unroll
        for (int i = 0; i < 16; i++) {
            int idx = i * 32 + lane;
            if (idx < 16 * 31) {
                float2 v = a2[gbase + idx];
                int r = idx / 31, j = idx - r * 31;
                uint2 t;
                t.x = f2tf(v.x);
                t.y = f2tf(v.y);
                *reinterpret_cast<uint2*>(smem + SM_A + (rbase + r) * STRDB + 8*j) = t;
            }
        }
    }

    // ---------------- Per-warp: degree + rare list --------------------------
    if (lane < 16) {
        const int r = rbase + lane;
        const int* ep = edges + (size_t)(row0 + r) * DD;
        int dg = 0;
        #pragma unroll
        for (int d = 0; d < DD; d++) dg += (ep[d] >= 0);
        if (dg < DD) {
            int p = atomicAdd(reinterpret_cast<int*>(smem + SM_NRARE), 1);
            reinterpret_cast<int*>(smem + SM_RARE)[p] = r | (dg << 8);
        }
    }

    // ---------------- Per-warp: bond sums (after bonds DMA) -----------------
    MBARRIER_WAIT_PARITY(smem_base + SM_MBAR, 0);
    if (lane < 16) {
        const int r = rbase + lane;
        const float* bb = reinterpret_cast<const float*>(smem + SM_BRAW) + r * (DD * FB);
        float bs[FB];
        #pragma unroll
        for (int f = 0; f < FB; f++) bs[f] = 0.f;
        #pragma unroll
        for (int d = 0; d < DD; d++)
            #pragma unroll
            for (int f = 0; f < FB; f++) bs[f] += bb[d * FB + f];
        float* bsum = reinterpret_cast<float*>(smem + SM_BSUM) + r * FB;
        #pragma unroll
        for (int f = 0; f < FB; f++) bsum[f] = bs[f];
        char* arow = smem + SM_A + r * STRDB;
        #pragma unroll
        for (int p = 0; p < 3; p++) {
            uint2 t;
            t.x = f2tf(bs[2*p]);
            t.y = f2tf(bs[2*p + 1]);
            *reinterpret_cast<uint2*>(arow + (62 + 2*p) * 4) = t;   // k 62..67
        }
        *reinterpret_cast<uint4*>(arow + 68 * 4) = make_uint4(0,0,0,0);  // k pad 68..71
    }

    // Pair barrier: rows wm..wm+31 fully staged by warps {pm, pm+4}.
    BAR_SYNC(pm + 1, 64);
    // B image complete
    MBARRIER_WAIT_PARITY(smem_base + SM_MBAR + 8, 0);

    // ---------------- TF32 tensor-core GEMM (single pass) -------------------
    // warp tile m32 x n64; per kk(9): 8 A LDS + 16 B LDS + 16 m16n8k8 MMAs.
    float acc0[8][4], acc1[8][4];
    #pragma unroll
    for (int j = 0; j < 8; j++)
        #pragma unroll
        for (int q = 0; q < 4; q++) { acc0[j][q] = 0.f; acc1[j][q] = 0.f; }

    // fragment base addresses (conflict-free: (12g + tig) mod 32 covers all banks)
    const uint32_t abase = smem_base + SM_A +
        (((uint32_t)(wm + (lane >> 2))) * STRDW + (lane & 3)) * 4;
    const uint32_t bbase = smem_base + SM_B +
        (((uint32_t)(wn + (lane >> 2))) * STRDW + (lane & 3)) * 4;

    #pragma unroll
    for (int kk = 0; kk < NKK; kk++) {
        const uint32_t ko = kk * 32;            // 8 words per k-step
        uint32_t a0[4], a1[4];
        a0[0] = lds32(abase + ko);                     // row g,    k tig
        a0[1] = lds32(abase + 8*STRDB + ko);           // row g+8,  k tig
        a0[2] = lds32(abase + ko + 16);                // row g,    k tig+4
        a0[3] = lds32(abase + 8*STRDB + ko + 16);      // row g+8,  k tig+4
        a1[0] = lds32(abase + 16*STRDB + ko);
        a1[1] = lds32(abase + 24*STRDB + ko);
        a1[2] = lds32(abase + 16*STRDB + ko + 16);
        a1[3] = lds32(abase + 24*STRDB + ko + 16);
        #pragma unroll
        for (int j = 0; j < 8; j++) {
            uint32_t b0 = lds32(bbase + (uint32_t)j * 8 * STRDB + ko);
            uint32_t b1 = lds32(bbase + (uint32_t)j * 8 * STRDB + ko + 16);
            mma_tf32(acc0[j], a0, b0, b1);
            mma_tf32(acc1[j], a1, b0, b1);
        }
    }

    // ---------------- Epilogue: bias + relu + STG.64 -------------------------
    {
        const float* bs = reinterpret_cast<const float*>(smem + SM_BSELF);
        const int rb  = wm + (lane >> 2);
        const int c00 = wn + 2 * (lane & 3);
        #pragma unroll
        for (int mi = 0; mi < 2; mi++) {
            const int rr = rb + 16 * mi;
            float* orow0 = out + (size_t)(row0 + rr) * CC;
            float* orow1 = out + (size_t)(row0 + rr + 8) * CC;
            #pragma unroll
            for (int j = 0; j < 8; j++) {
                const float (*av)[4] = mi ? acc1 : acc0;
                int c = c00 + 8 * j;
                float b0 = bs[c], b1 = bs[c + 1];
                float2 v0, v1;
                v0.x = fmaxf(av[j][0] + b0, 0.f);
                v0.y = fmaxf(av[j][1] + b1, 0.f);
                v1.x = fmaxf(av[j][2] + b0, 0.f);
                v1.y = fmaxf(av[j][3] + b1, 0.f);
                *reinterpret_cast<float2*>(orow0 + c) = v0;
                *reinterpret_cast<float2*>(orow1 + c) = v1;
            }
        }
    }
    __syncthreads();   // all epilogue STGs + bsum before rare-row RMW

    // ---------------- Rare rows (deg<5, ~3.8%): warp-parallel zni patch ------
    const int nr = *reinterpret_cast<int*>(smem + SM_NRARE);
    float* sfp = reinterpret_cast<float*>(smem + SM_SFW) + warp * 72;
    const float* bsum = reinterpret_cast<const float*>(smem + SM_BSUM);
    for (int i = warp; i < nr; i += 8) {
        int packed = reinterpret_cast<int*>(smem + SM_RARE)[i];
        int r  = packed & 0xFF;
        int dg = packed >> 8;
        int e[DD];
        #pragma unroll
        for (int d = 0; d < DD; d++) e[d] = edges[(size_t)(row0 + r) * DD + d];
        #pragma unroll
        for (int f = lane; f < FAN; f += 32) {
            float s;
            if (f < FA) {
                s = 0.f;
                #pragma unroll
                for (int d = 0; d < DD; d++)
                    if (e[d] >= 0) s += atoms[((size_t)(bidx * MM + e[d])) * FA + f];
            } else {
                s = bsum[r * FB + (f - FA)];
            }
            sfp[f] = s;
        }
        __syncwarp();
        const float4* bi4 = reinterpret_cast<const float4*>(b_inner) + dg * 32 + lane;
        const float4* w4  = reinterpret_cast<const float4*>(W_inner) + ((size_t)dg * FAN) * 32 + lane;
        float4 z = __ldg(bi4);
        #pragma unroll
        for (int f = 0; f < FAN; f++) {
            float  s = sfp[f];
            float4 w = __ldg(w4 + (size_t)f * 32);
            z.x = fmaf(s, w.x, z.x);
            z.y = fmaf(s, w.y, z.y);
            z.z = fmaf(s, w.z, z.z);
            z.w = fmaf(s, w.w, z.w);
        }
        float4* op = reinterpret_cast<float4*>(out + (size_t)(row0 + r) * CC) + lane;
        float4 cur = *op;
        cur.x += fmaxf(z.x, 0.f);
        cur.y += fmaxf(z.y, 0.f);
        cur.z += fmaxf(z.z, 0.f);
        cur.w += fmaxf(z.w, 0.f);
        *op = cur;
        __syncwarp();
    }
}

extern "C" void kernel_launch(void* const* d_in, const int* in_sizes, int n_in,
                              void* d_out, int out_size) {
    const float* atoms   = (const float*)d_in[0];
    const float* bonds   = (const float*)d_in[1];
    const int*   edges   = (const int*)  d_in[2];
    const float* W_inner = (const float*)d_in[3];
    const float* b_inner = (const float*)d_in[4];
    const float* W_self  = (const float*)d_in[5];
    const float* b_self  = (const float*)d_in[6];
    float* out = (float*)d_out;

    prep_kernel<<<KP, CC>>>(W_self);

    cudaFuncSetAttribute(tga_kernel, cudaFuncAttributeMaxDynamicSharedMemorySize, SM_TOTAL);

    cudaLaunchConfig_t cfg = {};
    cfg.gridDim  = dim3(BB, 1, 1);
    cfg.blockDim = dim3(NTHR, 1, 1);
    cfg.dynamicSmemBytes = SM_TOTAL;
    cfg.stream = 0;
    cudaLaunchAttribute at[1];
    at[0].id = cudaLaunchAttributeProgrammaticStreamSerialization;
    at[0].val.programmaticStreamSerializationAllowed = 1;
    cfg.attrs = at;
    cfg.numAttrs = 1;
    cudaLaunchKernelEx(&cfg, tga_kernel, atoms, bonds, edges,
                       W_inner, b_inner, b_self, out);
}

// round 17
// speedup vs baseline: 3.1019x; 1.0032x over previous
#include <cuda_runtime.h>
#include <cstdint>

// Problem constants
#define BB   2048
#define MM   128
#define FA   62
#define FB   6
#define DD   5
#define CC   128
#define FAN  68
#define NTHR 256
#define KP   72            // K padded to 9 mma-steps of 8
#define NKK  9
#define STRDW 76           // smem row stride in words (76%32=12 -> frag reads conflict-free)
#define STRDB (STRDW * 4)

// SMEM byte offsets
#define SM_A     0                       // 128 x 76 f32(tf32) = 38912
#define SM_B     38912                   // 128n x 76k f32(tf32) = 38912 (DMA dst)
#define SM_BSELF 77824                   // float[128]
#define SM_SFW   78336                   // 8 warps * 72 floats
#define SM_RARE  80640                   // int[128]
#define SM_NRARE 81152
#define SM_BSUM  81168                   // float[128*6] fp32 bond sums (tail reuse)
#define SM_MBAR  84240                   // 2 x 8B mbarriers (bonds, btile)
#define SM_BRAW  84256                   // raw bonds staging, 15360 B
#define SM_TOTAL 99616

#define BTILE_BYTES 38912
#define BRAW_BYTES  (MM * DD * FB * 4)   // 15360
// Pre-converted W_self^T tf32 image, exact smem layout, built once per launch.
__device__ __align__(16) unsigned char g_btile[BTILE_BYTES];

__device__ __forceinline__ uint32_t smem_to_u32(const void* p) {
    uint32_t a;
    asm("{ .reg .u64 t; cvta.to.shared.u64 t, %1; cvt.u32.u64 %0, t; }" : "=r"(a) : "l"(p));
    return a;
}
__device__ __forceinline__ uint32_t f2tf(float f) {   // round-to-nearest tf32
    uint32_t r;
    asm("cvt.rna.tf32.f32 %0, %1;" : "=r"(r) : "f"(f));
    return r;
}
__device__ __forceinline__ uint32_t lds32(uint32_t addr) {  // shared-space load
    uint32_t v;
    asm volatile("ld.shared.b32 %0, [%1];" : "=r"(v) : "r"(addr));
    return v;
}
__device__ __forceinline__ void mma_tf32(float* d, const uint32_t* a, uint32_t b0, uint32_t b1) {
    asm volatile("mma.sync.aligned.m16n8k8.row.col.f32.tf32.tf32.f32 "
                 "{%0,%1,%2,%3}, {%4,%5,%6,%7}, {%8,%9}, {%0,%1,%2,%3};"
                 : "+f"(d[0]), "+f"(d[1]), "+f"(d[2]), "+f"(d[3])
                 : "r"(a[0]), "r"(a[1]), "r"(a[2]), "r"(a[3]), "r"(b0), "r"(b1));
}
#define MBARRIER_INIT(mb, n) \
    asm volatile("mbarrier.init.shared.b64 [%0], %1;" :: "r"((uint32_t)(mb)), "r"((uint32_t)(n)) : "memory")
#define MBARRIER_EXPECT_TX(mb, bytes) \
    asm volatile("mbarrier.arrive.expect_tx.shared.b64 _, [%0], %1;" :: "r"((uint32_t)(mb)), "r"((uint32_t)(bytes)) : "memory")
#define MBARRIER_WAIT_PARITY(mb, ph) do { \
    uint32_t _mb = (uint32_t)(mb), _ph = (uint32_t)(ph), _done; \
    asm volatile("{ .reg .pred p; mbarrier.try_wait.parity.acquire.cta.shared::cta.b64 p, [%1], %2; selp.b32 %0, 1, 0, p; }" \
                 : "=r"(_done) : "r"(_mb), "r"(_ph) : "memory"); \
    if (!_done) { \
        asm volatile("{ .reg .pred P1; WL_%=: mbarrier.try_wait.parity.acquire.cta.shared::cta.b64 P1, [%0], %1, 0x989680; @P1 bra.uni WD_%=; bra.uni WL_%=; WD_%=: }" \
                     :: "r"(_mb), "r"(_ph) : "memory"); \
    } \
} while (0)
#define BAR_SYNC(id, cnt) \
    asm volatile("bar.sync %0, %1;" :: "r"(id), "r"(cnt) : "memory")
__device__ __forceinline__ void bulk_g2s(uint32_t dst, const void* src, uint32_t bytes, uint32_t mbar) {
    asm volatile("cp.async.bulk.shared::cta.global.mbarrier::complete_tx::bytes [%0], [%1], %2, [%3];"
                 :: "r"(dst), "l"(src), "r"(bytes), "r"(mbar) : "memory");
}

// ---------------- Prep: W_self^T -> tf32-rounded f32 image ------------------
__global__ void prep_kernel(const float* __restrict__ W_self) {
    const int k = blockIdx.x;        // 0..KP-1
    const int n = threadIdx.x;       // 0..127
    uint32_t v = 0u;
    if (k < FAN) v = f2tf(W_self[(size_t)k * CC + n]);
    *reinterpret_cast<uint32_t*>(g_btile + ((uint32_t)n * STRDW + k) * 4) = v;
    asm volatile("griddepcontrol.launch_dependents;");
}

__global__ __launch_bounds__(NTHR, 2)
void tga_kernel(const float* __restrict__ atoms,
                const float* __restrict__ bonds,
                const int*   __restrict__ edges,
                const float* __restrict__ W_inner,
                const float* __restrict__ b_inner,
                const float* __restrict__ b_self,
                float* __restrict__ out) {
    extern __shared__ char smem[];
    const uint32_t smem_base = smem_to_u32(smem);
    const int tid  = threadIdx.x;
    const int lane = tid & 31;
    const int warp = tid >> 5;
    const int row0 = blockIdx.x * MM;      // one batch per CTA
    const int bidx = blockIdx.x;

    // per-warp tile coordinates (GEMM: m32 x n64; pair {w, w+4} shares m rows)
    const int pm   = warp & 3;
    const int half = warp >> 2;
    const int rbase = pm * 32 + half * 16; // 16 A-rows owned by this warp
    const int wm = pm * 32;
    const int wn = half * 64;

    if (tid == 0) {
        *reinterpret_cast<int*>(smem + SM_NRARE) = 0;
        MBARRIER_INIT(smem_base + SM_MBAR, 1);       // bonds
        MBARRIER_INIT(smem_base + SM_MBAR + 8, 1);   // B image
    }
    __syncthreads();

    // ---------------- DMAs -----------------------------------------------
    if (tid == 0) {
        MBARRIER_EXPECT_TX(smem_base + SM_MBAR, BRAW_BYTES);
        bulk_g2s(smem_base + SM_BRAW, bonds + (size_t)row0 * DD * FB,
                 BRAW_BYTES, smem_base + SM_MBAR);
        asm volatile("griddepcontrol.wait;" ::: "memory");   // prep's g_btile ready
        MBARRIER_EXPECT_TX(smem_base + SM_MBAR + 8, BTILE_BYTES);
        bulk_g2s(smem_base + SM_B, g_btile, BTILE_BYTES, smem_base + SM_MBAR + 8);
    }
    if (tid < CC) reinterpret_cast<float*>(smem + SM_BSELF)[tid] = b_self[tid];

    // ---------------- Per-warp: stage own 16 atom rows as tf32 -------------
    {
        const float2* a2 = reinterpret_cast<const float2*>(atoms);
        const size_t gbase = (size_t)(row0 + rbase) * 31;   // rows contiguous, flat
        #pragma unroll
        for (int i = 0; i < 16; i++) {
            int idx = i * 32 + lane;
            if (idx < 16 * 31) {
                float2 v = a2[gbase + idx];
                int r = idx / 31, j = idx - r * 31;
                uint2 t;
                t.x = f2tf(v.x);
                t.y = f2tf(v.y);
                *reinterpret_cast<uint2*>(smem + SM_A + (rbase + r) * STRDB + 8*j) = t;
            }
        }
    }

    // ---------------- Per-warp: degree + rare list --------------------------
    if (lane < 16) {
        const int r = rbase + lane;
        const int* ep = edges + (size_t)(row0 + r) * DD;
        int dg = 0;
        #pragma unroll
        for (int d = 0; d < DD; d++) dg += (ep[d] >= 0);
        if (dg < DD) {
            int p = atomicAdd(reinterpret_cast<int*>(smem + SM_NRARE), 1);
            reinterpret_cast<int*>(smem + SM_RARE)[p] = r | (dg << 8);
        }
    }

    // ---------------- Per-warp: bond sums (after bonds DMA) -----------------
    MBARRIER_WAIT_PARITY(smem_base + SM_MBAR, 0);
    if (lane < 16) {
        const int r = rbase + lane;
        const float* bb = reinterpret_cast<const float*>(smem + SM_BRAW) + r * (DD * FB);
        float bs[FB];
        #pragma unroll
        for (int f = 0; f < FB; f++) bs[f] = 0.f;
        #pragma unroll
        for (int d = 0; d < DD; d++)
            #pragma unroll
            for (int f = 0; f < FB; f++) bs[f] += bb[d * FB + f];
        float* bsum = reinterpret_cast<float*>(smem + SM_BSUM) + r * FB;
        #pragma unroll
        for (int f = 0; f < FB; f++) bsum[f] = bs[f];
        char* arow = smem + SM_A + r * STRDB;
        #pragma unroll
        for (int p = 0; p < 3; p++) {
            uint2 t;
            t.x = f2tf(bs[2*p]);
            t.y = f2tf(bs[2*p + 1]);
            *reinterpret_cast<uint2*>(arow + (62 + 2*p) * 4) = t;   // k 62..67
        }
        *reinterpret_cast<uint4*>(arow + 68 * 4) = make_uint4(0,0,0,0);  // k pad 68..71
    }

    // Pair barrier: rows wm..wm+31 fully staged by warps {pm, pm+4}.
    BAR_SYNC(pm + 1, 64);
    // B image complete
    MBARRIER_WAIT_PARITY(smem_base + SM_MBAR + 8, 0);

    // ---------------- TF32 tensor-core GEMM (single pass) -------------------
    // warp tile m32 x n64; per kk(9): 8 A LDS + 16 B LDS + 16 m16n8k8 MMAs.
    float acc0[8][4], acc1[8][4];
    #pragma unroll
    for (int j = 0; j < 8; j++)
        #pragma unroll
        for (int q = 0; q < 4; q++) { acc0[j][q] = 0.f; acc1[j][q] = 0.f; }

    // fragment base addresses (conflict-free: (12g + tig) mod 32 covers all banks)
    const uint32_t abase = smem_base + SM_A +
        (((uint32_t)(wm + (lane >> 2))) * STRDW + (lane & 3)) * 4;
    const uint32_t bbase = smem_base + SM_B +
        (((uint32_t)(wn + (lane >> 2))) * STRDW + (lane & 3)) * 4;

    #pragma unroll
    for (int kk = 0; kk < NKK; kk++) {
        const uint32_t ko = kk * 32;            // 8 words per k-step
        uint32_t a0[4], a1[4];
        a0[0] = lds32(abase + ko);                     // row g,    k tig
        a0[1] = lds32(abase + 8*STRDB + ko);           // row g+8,  k tig
        a0[2] = lds32(abase + ko + 16);                // row g,    k tig+4
        a0[3] = lds32(abase + 8*STRDB + ko + 16);      // row g+8,  k tig+4
        a1[0] = lds32(abase + 16*STRDB + ko);
        a1[1] = lds32(abase + 24*STRDB + ko);
        a1[2] = lds32(abase + 16*STRDB + ko + 16);
        a1[3] = lds32(abase + 24*STRDB + ko + 16);
        #pragma unroll
        for (int j = 0; j < 8; j++) {
            uint32_t b0 = lds32(bbase + (uint32_t)j * 8 * STRDB + ko);
            uint32_t b1 = lds32(bbase + (uint32_t)j * 8 * STRDB + ko + 16);
            mma_tf32(acc0[j], a0, b0, b1);
            mma_tf32(acc1[j], a1, b0, b1);
        }
    }

    // ---------------- Epilogue: bias + relu + STG.64 -------------------------
    {
        const float* bs = reinterpret_cast<const float*>(smem + SM_BSELF);
        const int rb  = wm + (lane >> 2);
        const int c00 = wn + 2 * (lane & 3);
        #pragma unroll
        for (int mi = 0; mi < 2; mi++) {
            const int rr = rb + 16 * mi;
            float* orow0 = out + (size_t)(row0 + rr) * CC;
            float* orow1 = out + (size_t)(row0 + rr + 8) * CC;
            #pragma unroll
            for (int j = 0; j < 8; j++) {
                const float (*av)[4] = mi ? acc1 : acc0;
                int c = c00 + 8 * j;
                float b0 = bs[c], b1 = bs[c + 1];
                float2 v0, v1;
                v0.x = fmaxf(av[j][0] + b0, 0.f);
                v0.y = fmaxf(av[j][1] + b1, 0.f);
                v1.x = fmaxf(av[j][2] + b0, 0.f);
                v1.y = fmaxf(av[j][3] + b1, 0.f);
                *reinterpret_cast<float2*>(orow0 + c) = v0;
                *reinterpret_cast<float2*>(orow1 + c) = v1;
            }
        }
    }
    __syncthreads();   // all epilogue STGs + bsum before rare-row RMW

    // ---------------- Rare rows (deg<5, ~3.8%): warp-parallel zni patch ------
    const int nr = *reinterpret_cast<int*>(smem + SM_NRARE);
    float* sfp = reinterpret_cast<float*>(smem + SM_SFW) + warp * 72;
    const float* bsum = reinterpret_cast<const float*>(smem + SM_BSUM);
    for (int i = warp; i < nr; i += 8) {
        int packed = reinterpret_cast<int*>(smem + SM_RARE)[i];
        int r  = packed & 0xFF;
        int dg = packed >> 8;
        int e[DD];
        #pragma unroll
        for (int d = 0; d < DD; d++) e[d] = edges[(size_t)(row0 + r) * DD + d];
        #pragma unroll
        for (int f = lane; f < FAN; f += 32) {
            float s;
            if (f < FA) {
                s = 0.f;
                #pragma unroll
                for (int d = 0; d < DD; d++)
                    if (e[d] >= 0) s += atoms[((size_t)(bidx * MM + e[d])) * FA + f];
            } else {
                s = bsum[r * FB + (f - FA)];
            }
            sfp[f] = s;
        }
        __syncwarp();
        const float4* bi4 = reinterpret_cast<const float4*>(b_inner) + dg * 32 + lane;
        const float4* w4  = reinterpret_cast<const float4*>(W_inner) + ((size_t)dg * FAN) * 32 + lane;
        float4 z = __ldg(bi4);
        #pragma unroll
        for (int f = 0; f < FAN; f++) {
            float  s = sfp[f];
            float4 w = __ldg(w4 + (size_t)f * 32);
            z.x = fmaf(s, w.x, z.x);
            z.y = fmaf(s, w.y, z.y);
            z.z = fmaf(s, w.z, z.z);
            z.w = fmaf(s, w.w, z.w);
        }
        float4* op = reinterpret_cast<float4*>(out + (size_t)(row0 + r) * CC) + lane;
        float4 cur = *op;
        cur.x += fmaxf(z.x, 0.f);
        cur.y += fmaxf(z.y, 0.f);
        cur.z += fmaxf(z.z, 0.f);
        cur.w += fmaxf(z.w, 0.f);
        *op = cur;
        __syncwarp();
    }
}

extern "C" void kernel_launch(void* const* d_in, const int* in_sizes, int n_in,
                              void* d_out, int out_size) {
    const float* atoms   = (const float*)d_in[0];
    const float* bonds   = (const float*)d_in[1];
    const int*   edges   = (const int*)  d_in[2];
    const float* W_inner = (const float*)d_in[3];
    const float* b_inner = (const float*)d_in[4];
    const float* W_self  = (const float*)d_in[5];
    const float* b_self  = (const float*)d_in[6];
    float* out = (float*)d_out;

    prep_kernel<<<KP, CC>>>(W_self);

    cudaFuncSetAttribute(tga_kernel, cudaFuncAttributeMaxDynamicSharedMemorySize, SM_TOTAL);

    cudaLaunchConfig_t cfg = {};
    cfg.gridDim  = dim3(BB, 1, 1);
    cfg.blockDim = dim3(NTHR, 1, 1);
    cfg.dynamicSmemBytes = SM_TOTAL;
    cfg.stream = 0;
    cudaLaunchAttribute at[1];
    at[0].id = cudaLaunchAttributeProgrammaticStreamSerialization;
    at[0].val.programmaticStreamSerializationAllowed = 1;
    cfg.attrs = at;
    cfg.numAttrs = 1;
    cudaLaunchKernelEx(&cfg, tga_kernel, atoms, bonds, edges,
                       W_inner, b_inner, b_self, out);
}